// round 8
// baseline (speedup 1.0000x reference)
#include <cuda_runtime.h>
#include <cstddef>

#define H 256
#define NCAP 100000
#define ECAP 1600000
#define BCAP 256
#define BN_EPS 1e-5f

// ---------------- scratch (static __device__, allocation-free) ----------------
__device__ float g_bufA[(size_t)NCAP * H];   // GEMM output h' = h * dinv[row]
__device__ float g_bufC[(size_t)NCAP * H];   // h1 (post relu/bn) = residual
__device__ float g_wdeg[NCAP];               // weighted degree (float)
__device__ int   g_count[NCAP];              // edge count per dst
__device__ int   g_rowptr[NCAP + 1];
__device__ int   g_fill[NCAP];
__device__ int2  g_edges[ECAP];              // CSR: {src, w_bits} per slot
__device__ float g_dinv[NCAP];
__device__ float g_cnt[BCAP];
__device__ float g_pool[BCAP * H];
__device__ float g_emb[BCAP * H];
__device__ float g_z1[BCAP * 256];
__device__ float g_z2[BCAP * 128];
__device__ float g_bnA1[H], g_bnB1[H], g_bnA2[H], g_bnB2[H];

__device__ __forceinline__ void red_add_v4(float* addr, float x, float y, float z, float w) {
    asm volatile("red.global.add.v4.f32 [%0], {%1, %2, %3, %4};"
                 :: "l"(addr), "f"(x), "f"(y), "f"(z), "f"(w) : "memory");
}

// ---------------- zero accumulators ----------------
__global__ void k_zero(int n_nodes, int nb) {
    int total = 2 * n_nodes + nb + nb * H;
    for (int i = blockIdx.x * blockDim.x + threadIdx.x; i < total;
         i += gridDim.x * blockDim.x) {
        if (i < n_nodes) { g_wdeg[i] = 0.f; }
        else if (i < 2 * n_nodes) { g_count[i - n_nodes] = 0; }
        else if (i < 2 * n_nodes + nb) { g_cnt[i - 2 * n_nodes] = 0.f; }
        else { g_pool[i - 2 * n_nodes - nb] = 0.f; }
    }
}

// ---------------- histogram: count + weighted degree per dst ----------------
__global__ void k_hist(const int* __restrict__ dst, const float* __restrict__ ew, int E) {
    for (int e = blockIdx.x * blockDim.x + threadIdx.x; e < E;
         e += gridDim.x * blockDim.x) {
        int d = dst[e];
        atomicAdd(&g_count[d], 1);
        atomicAdd(&g_wdeg[d], ew[e]);
    }
}

// ---------------- dinv + per-graph node counts ----------------
__global__ void k_prep(const int* __restrict__ batch, int n_nodes) {
    for (int i = blockIdx.x * blockDim.x + threadIdx.x; i < n_nodes;
         i += gridDim.x * blockDim.x) {
        g_dinv[i] = rsqrtf(g_wdeg[i] + 1.0f);
        atomicAdd(&g_cnt[batch[i]], 1.0f);
    }
}

// ---------------- fold BN params: out = A*x + B (bias folded in) ----------------
__global__ void k_bnprep(const float* b1, const float* g1, const float* be1,
                         const float* rm1, const float* rv1,
                         const float* b2, const float* g2, const float* be2,
                         const float* rm2, const float* rv2) {
    int c = threadIdx.x;
    {
        float A = g1[c] * rsqrtf(rv1[c] + BN_EPS);
        g_bnA1[c] = A;
        g_bnB1[c] = be1[c] + (b1[c] - rm1[c]) * A;
    }
    {
        float A = g2[c] * rsqrtf(rv2[c] + BN_EPS);
        g_bnA2[c] = A;
        g_bnB2[c] = be2[c] + (b2[c] - rm2[c]) * A;
    }
}

// ---------------- single-block exclusive scan of g_count -> g_rowptr/g_fill ----------------
__global__ void k_scan(int N) {
    __shared__ int warp_sums[32];
    __shared__ int s_carry;
    int t = threadIdx.x, lane = t & 31, w = t >> 5;
    if (t == 0) s_carry = 0;
    __syncthreads();
    for (int base = 0; base < N; base += 4096) {
        int i0 = base + t * 4;
        int v[4];
        #pragma unroll
        for (int j = 0; j < 4; j++) v[j] = (i0 + j < N) ? g_count[i0 + j] : 0;
        int s = v[0] + v[1] + v[2] + v[3];
        int x = s;
        #pragma unroll
        for (int o = 1; o < 32; o <<= 1) {
            int y = __shfl_up_sync(0xffffffffu, x, o);
            if (lane >= o) x += y;
        }
        if (lane == 31) warp_sums[w] = x;
        __syncthreads();
        if (w == 0) {
            int ws = warp_sums[lane];
            #pragma unroll
            for (int o = 1; o < 32; o <<= 1) {
                int y = __shfl_up_sync(0xffffffffu, ws, o);
                if (lane >= o) ws += y;
            }
            warp_sums[lane] = ws;
        }
        __syncthreads();
        int excl = x - s + (w > 0 ? warp_sums[w - 1] : 0) + s_carry;
        #pragma unroll
        for (int j = 0; j < 4; j++) {
            if (i0 + j < N) { g_rowptr[i0 + j] = excl; g_fill[i0 + j] = excl; }
            excl += v[j];
        }
        __syncthreads();
        if (t == 1023) s_carry = excl;
        __syncthreads();
    }
    if (t == 0) g_rowptr[N] = s_carry;
}

// ---------------- scatter edges into CSR slots (interleaved {src, w}) ----------------
__global__ void k_build(const int* __restrict__ src, const int* __restrict__ dst,
                        const float* __restrict__ ew, int E) {
    for (int e = blockIdx.x * blockDim.x + threadIdx.x; e < E;
         e += gridDim.x * blockDim.x) {
        int d = dst[e];
        int p = atomicAdd(&g_fill[d], 1);
        g_edges[p] = make_int2(src[e], __float_as_int(ew[e]));
    }
}

// ---------------- fp32 GEMM: C[r,c] = (A[M,K] @ W[K,Nc])[r,c] * scale[r] ----------------
// 128x128 tile, BK=8, 256 threads, 8x8 microtile (2x2 blocks of 4), double-buffered.
__global__ __launch_bounds__(256, 2)
void k_gemm(const float* __restrict__ A, const float* __restrict__ W,
            float* __restrict__ C, const float* __restrict__ scale,
            int M, int K, int Nc) {
    __shared__ float As[2][8][132];   // [k][m], padded
    __shared__ float Bs[2][8][128];   // [k][n]

    int t = threadIdx.x;
    int tx = t & 15, ty = t >> 4;
    int row0 = blockIdx.y * 128;
    int col0 = blockIdx.x * 128;

    int a_row = t >> 1;           // 0..127
    int a_k   = (t & 1) * 4;      // 0 or 4
    int b_k   = t >> 5;           // 0..7
    int b_col = (t & 31) * 4;     // 0..124

    float4 a_reg, b_reg;

    // prefetch tile 0
    {
        int gr = row0 + a_row;
        a_reg = make_float4(0.f, 0.f, 0.f, 0.f);
        if (gr < M) a_reg = *(const float4*)(A + (size_t)gr * K + a_k);
        b_reg = *(const float4*)(W + (size_t)b_k * Nc + col0 + b_col);
        As[0][a_k + 0][a_row] = a_reg.x;
        As[0][a_k + 1][a_row] = a_reg.y;
        As[0][a_k + 2][a_row] = a_reg.z;
        As[0][a_k + 3][a_row] = a_reg.w;
        *(float4*)&Bs[0][b_k][b_col] = b_reg;
    }
    __syncthreads();

    float acc[8][8] = {};
    int nt = K / 8;
    int buf = 0;

    for (int it = 0; it < nt; it++) {
        if (it + 1 < nt) {
            int k0 = (it + 1) * 8;
            int gr = row0 + a_row;
            a_reg = make_float4(0.f, 0.f, 0.f, 0.f);
            if (gr < M) a_reg = *(const float4*)(A + (size_t)gr * K + k0 + a_k);
            b_reg = *(const float4*)(W + (size_t)(k0 + b_k) * Nc + col0 + b_col);
        }

        #pragma unroll
        for (int k = 0; k < 8; k++) {
            float4 a0 = *(const float4*)&As[buf][k][ty * 4];
            float4 a1 = *(const float4*)&As[buf][k][64 + ty * 4];
            float4 b0 = *(const float4*)&Bs[buf][k][tx * 4];
            float4 b1 = *(const float4*)&Bs[buf][k][64 + tx * 4];
            float a[8] = {a0.x, a0.y, a0.z, a0.w, a1.x, a1.y, a1.z, a1.w};
            float b[8] = {b0.x, b0.y, b0.z, b0.w, b1.x, b1.y, b1.z, b1.w};
            #pragma unroll
            for (int i = 0; i < 8; i++)
                #pragma unroll
                for (int j = 0; j < 8; j++)
                    acc[i][j] += a[i] * b[j];
        }

        if (it + 1 < nt) {
            int nb = buf ^ 1;
            As[nb][a_k + 0][a_row] = a_reg.x;
            As[nb][a_k + 1][a_row] = a_reg.y;
            As[nb][a_k + 2][a_row] = a_reg.z;
            As[nb][a_k + 3][a_row] = a_reg.w;
            *(float4*)&Bs[nb][b_k][b_col] = b_reg;
            __syncthreads();
            buf = nb;
        }
    }

    #pragma unroll
    for (int i = 0; i < 8; i++) {
        int r = (i < 4) ? (ty * 4 + i) : (64 + ty * 4 + i - 4);
        int gr = row0 + r;
        if (gr < M) {
            float s = scale[gr];
            float4 o0 = make_float4(acc[i][0] * s, acc[i][1] * s, acc[i][2] * s, acc[i][3] * s);
            float4 o1 = make_float4(acc[i][4] * s, acc[i][5] * s, acc[i][6] * s, acc[i][7] * s);
            *(float4*)(C + (size_t)gr * Nc + col0 + tx * 4) = o0;
            *(float4*)(C + (size_t)gr * Nc + col0 + 64 + tx * 4) = o1;
        }
    }
}

// ---------------- CSR gather core: acc = h'[d] + sum_e w*h'[src] ----------------
__device__ __forceinline__ float4 gather_acc(const float* __restrict__ hp, int d, int c) {
    int beg = __ldg(&g_rowptr[d]), end = __ldg(&g_rowptr[d + 1]);
    float4 acc = *(const float4*)(hp + (size_t)d * H + c);  // self-loop term
    int e = beg;
    for (; e + 4 <= end; e += 4) {
        int2 p0 = __ldg(&g_edges[e + 0]);
        int2 p1 = __ldg(&g_edges[e + 1]);
        int2 p2 = __ldg(&g_edges[e + 2]);
        int2 p3 = __ldg(&g_edges[e + 3]);
        float4 v0 = *(const float4*)(hp + (size_t)p0.x * H + c);
        float4 v1 = *(const float4*)(hp + (size_t)p1.x * H + c);
        float4 v2 = *(const float4*)(hp + (size_t)p2.x * H + c);
        float4 v3 = *(const float4*)(hp + (size_t)p3.x * H + c);
        float w0 = __int_as_float(p0.y), w1 = __int_as_float(p1.y);
        float w2 = __int_as_float(p2.y), w3 = __int_as_float(p3.y);
        acc.x += w0 * v0.x + w1 * v1.x + w2 * v2.x + w3 * v3.x;
        acc.y += w0 * v0.y + w1 * v1.y + w2 * v2.y + w3 * v3.y;
        acc.z += w0 * v0.z + w1 * v1.z + w2 * v2.z + w3 * v3.z;
        acc.w += w0 * v0.w + w1 * v1.w + w2 * v2.w + w3 * v3.w;
    }
    for (; e < end; e++) {
        int2 p = __ldg(&g_edges[e]);
        float w = __int_as_float(p.y);
        float4 v = *(const float4*)(hp + (size_t)p.x * H + c);
        acc.x += w * v.x; acc.y += w * v.y; acc.z += w * v.z; acc.w += w * v.w;
    }
    return acc;
}

// ---------------- gather layer 1: out = relu(bnA*(dinv[d]*acc) + bnB) ----------------
__global__ void k_gather1(const float* __restrict__ hp, float* __restrict__ out, int N) {
    int lane = threadIdx.x & 63;
    int d = blockIdx.x * 4 + (threadIdx.x >> 6);
    if (d >= N) return;
    int c = lane * 4;
    float4 acc = gather_acc(hp, d, c);
    float di = g_dinv[d];
    float4 A = *(const float4*)&g_bnA1[c];
    float4 Bv = *(const float4*)&g_bnB1[c];
    float4 o;
    o.x = fmaxf(A.x * (di * acc.x) + Bv.x, 0.f);
    o.y = fmaxf(A.y * (di * acc.y) + Bv.y, 0.f);
    o.z = fmaxf(A.z * (di * acc.z) + Bv.z, 0.f);
    o.w = fmaxf(A.w * (di * acc.w) + Bv.w, 0.f);
    *(float4*)(out + (size_t)d * H + c) = o;
}

// ---------------- gather layer 2 + residual + pool accumulate ----------------
__global__ void k_gather2(const float* __restrict__ hp, const float* __restrict__ res,
                          const int* __restrict__ batch, int N) {
    int lane = threadIdx.x & 63;
    int d = blockIdx.x * 4 + (threadIdx.x >> 6);
    if (d >= N) return;
    int c = lane * 4;
    float4 acc = gather_acc(hp, d, c);
    float di = g_dinv[d];
    float4 A = *(const float4*)&g_bnA2[c];
    float4 Bv = *(const float4*)&g_bnB2[c];
    float4 r = *(const float4*)(res + (size_t)d * H + c);
    float vx = fmaxf(A.x * (di * acc.x) + Bv.x, 0.f) + r.x;
    float vy = fmaxf(A.y * (di * acc.y) + Bv.y, 0.f) + r.y;
    float vz = fmaxf(A.z * (di * acc.z) + Bv.z, 0.f) + r.z;
    float vw = fmaxf(A.w * (di * acc.w) + Bv.w, 0.f) + r.w;
    int b = __ldg(&batch[d]);
    red_add_v4(&g_pool[(size_t)b * H + c], vx, vy, vz, vw);
}

// ---------------- per-graph mean + write emb output ----------------
__global__ void k_emb(float* __restrict__ out, int out_size, int nb) {
    int i = blockIdx.x * blockDim.x + threadIdx.x;
    if (i < nb * H) {
        int b = i >> 8;
        float e = g_pool[i] / fmaxf(g_cnt[b], 1.0f);
        g_emb[i] = e;
        if (out_size >= nb * 2 + nb * H)
            out[nb * 2 + i] = e;
    }
}

// ---------------- classifier MLP layer: out = relu(bn(in @ W + b)) ----------------
__global__ void k_mlp(const float* __restrict__ in, const float* __restrict__ W,
                      const float* __restrict__ bb, const float* __restrict__ gg,
                      const float* __restrict__ be, const float* __restrict__ rm,
                      const float* __restrict__ rv, float* __restrict__ out,
                      int Kin, int Nout) {
    extern __shared__ float sh[];
    int b = blockIdx.x, t = threadIdx.x;
    for (int k = t; k < Kin; k += blockDim.x) sh[k] = in[(size_t)b * Kin + k];
    __syncthreads();
    if (t < Nout) {
        float acc = 0.f;
        for (int k = 0; k < Kin; k++) acc += sh[k] * W[(size_t)k * Nout + t];
        acc += bb[t];
        acc = (acc - rm[t]) * rsqrtf(rv[t] + BN_EPS) * gg[t] + be[t];
        out[(size_t)b * Nout + t] = fmaxf(acc, 0.f);
    }
}

// ---------------- final logits ----------------
__global__ void k_logits(const float* __restrict__ W, const float* __restrict__ bb,
                         float* __restrict__ out, int nb) {
    int i = blockIdx.x * blockDim.x + threadIdx.x;
    if (i < nb * 2) {
        int b = i >> 1, o = i & 1;
        float acc = bb[o];
        for (int k = 0; k < 128; k++) acc += g_z2[b * 128 + k] * W[k * 2 + o];
        out[i] = acc;
    }
}

extern "C" void kernel_launch(void* const* d_in, const int* in_sizes, int n_in,
                              void* d_out, int out_size) {
    const float* x     = (const float*)d_in[0];
    const int*   ei    = (const int*)d_in[1];
    const float* ew    = (const float*)d_in[2];
    const int*   batch = (const int*)d_in[3];
    const float* W1  = (const float*)d_in[4];
    const float* b1  = (const float*)d_in[5];
    const float* g1  = (const float*)d_in[6];
    const float* be1 = (const float*)d_in[7];
    const float* rm1 = (const float*)d_in[8];
    const float* rv1 = (const float*)d_in[9];
    const float* W2  = (const float*)d_in[10];
    const float* b2  = (const float*)d_in[11];
    const float* g2  = (const float*)d_in[12];
    const float* be2 = (const float*)d_in[13];
    const float* rm2 = (const float*)d_in[14];
    const float* rv2 = (const float*)d_in[15];
    const float* cW1  = (const float*)d_in[16];
    const float* cb1  = (const float*)d_in[17];
    const float* cg1  = (const float*)d_in[18];
    const float* cbe1 = (const float*)d_in[19];
    const float* crm1 = (const float*)d_in[20];
    const float* crv1 = (const float*)d_in[21];
    const float* cW2  = (const float*)d_in[22];
    const float* cb2  = (const float*)d_in[23];
    const float* cg2  = (const float*)d_in[24];
    const float* cbe2 = (const float*)d_in[25];
    const float* crm2 = (const float*)d_in[26];
    const float* crv2 = (const float*)d_in[27];
    const float* cW3  = (const float*)d_in[28];
    const float* cb3  = (const float*)d_in[29];

    int DIN = in_sizes[4] / H;          // 128
    int N   = in_sizes[0] / DIN;        // 100000
    int E   = in_sizes[2];              // 1600000
    int B   = (out_size % (2 + H) == 0) ? out_size / (2 + H) : BCAP;  // 256

    const int* src = ei;
    const int* dst = ei + E;

    float *bufA, *bufC, *emb, *z1, *z2, *dinv;
    cudaGetSymbolAddress((void**)&bufA, g_bufA);
    cudaGetSymbolAddress((void**)&bufC, g_bufC);
    cudaGetSymbolAddress((void**)&emb,  g_emb);
    cudaGetSymbolAddress((void**)&z1,   g_z1);
    cudaGetSymbolAddress((void**)&z2,   g_z2);
    cudaGetSymbolAddress((void**)&dinv, g_dinv);

    float* out = (float*)d_out;

    // prep: histogram, dinv, BN fold, CSR build
    int zt = 2 * N + B + B * H;
    k_zero<<<(zt + 255) / 256, 256>>>(N, B);
    k_hist<<<2048, 256>>>(dst, ew, E);
    k_prep<<<512, 256>>>(batch, N);
    k_bnprep<<<1, H>>>(b1, g1, be1, rm1, rv1, b2, g2, be2, rm2, rv2);
    k_scan<<<1, 1024>>>(N);
    k_build<<<2048, 256>>>(src, dst, ew, E);

    // layer 1
    dim3 gg1((H + 127) / 128, (N + 127) / 128);
    k_gemm<<<gg1, 256>>>(x, W1, bufA, dinv, N, DIN, H);
    k_gather1<<<(N + 3) / 4, 256>>>(bufA, bufC, N);

    // layer 2
    k_gemm<<<gg1, 256>>>(bufC, W2, bufA, dinv, N, H, H);
    k_gather2<<<(N + 3) / 4, 256>>>(bufA, bufC, batch, N);

    // pooling + classifier
    k_emb<<<(B * H + 255) / 256, 256>>>(out, out_size, B);
    k_mlp<<<B, 256, H * sizeof(float)>>>(emb, cW1, cb1, cg1, cbe1, crm1, crv1, z1, H, 256);
    k_mlp<<<B, 256, 256 * sizeof(float)>>>(z1, cW2, cb2, cg2, cbe2, crm2, crv2, z2, 256, 128);
    k_logits<<<(B * 2 + 255) / 256, 256>>>(cW3, cb3, out, B);
}

// round 9
// speedup vs baseline: 1.2395x; 1.2395x over previous
#include <cuda_runtime.h>
#include <mma.h>
#include <cstddef>

using namespace nvcuda;

#define H 256
#define NCAP 100000
#define NPAD 100096      // NCAP rounded up to 128 (full-tile GEMM stores)
#define ECAP 1600000
#define BCAP 256
#define BN_EPS 1e-5f

// ---------------- scratch (static __device__, allocation-free) ----------------
__device__ float g_bufA[(size_t)NPAD * H];   // GEMM output h' = h * dinv[row] (row-padded)
__device__ float g_bufC[(size_t)NCAP * H];   // h1 (post relu/bn) = residual
__device__ float g_wdeg[NCAP];               // weighted degree (float)
__device__ int   g_count[NCAP];              // edge count per dst
__device__ int   g_rowptr[NCAP + 1];
__device__ int   g_fill[NCAP];
__device__ int   g_csrc[ECAP];               // CSR: src node per edge slot
__device__ float g_cw[ECAP];                 // CSR: edge weight per slot
__device__ float g_dinv[NCAP];
__device__ float g_cnt[BCAP];
__device__ float g_pool[BCAP * H];
__device__ float g_emb[BCAP * H];
__device__ float g_z1[BCAP * 256];
__device__ float g_z2[BCAP * 128];
__device__ float g_bnA1[H], g_bnB1[H], g_bnA2[H], g_bnB2[H];

__device__ __forceinline__ void red_add_v4(float* addr, float x, float y, float z, float w) {
    asm volatile("red.global.add.v4.f32 [%0], {%1, %2, %3, %4};"
                 :: "l"(addr), "f"(x), "f"(y), "f"(z), "f"(w) : "memory");
}

// ---------------- zero accumulators ----------------
__global__ void k_zero(int n_nodes, int nb) {
    int total = 2 * n_nodes + nb + nb * H;
    for (int i = blockIdx.x * blockDim.x + threadIdx.x; i < total;
         i += gridDim.x * blockDim.x) {
        if (i < n_nodes) { g_wdeg[i] = 0.f; }
        else if (i < 2 * n_nodes) { g_count[i - n_nodes] = 0; }
        else if (i < 2 * n_nodes + nb) { g_cnt[i - 2 * n_nodes] = 0.f; }
        else { g_pool[i - 2 * n_nodes - nb] = 0.f; }
    }
}

// ---------------- histogram: count + weighted degree per dst ----------------
__global__ void k_hist(const int* __restrict__ dst, const float* __restrict__ ew, int E) {
    for (int e = blockIdx.x * blockDim.x + threadIdx.x; e < E;
         e += gridDim.x * blockDim.x) {
        int d = dst[e];
        atomicAdd(&g_count[d], 1);
        atomicAdd(&g_wdeg[d], ew[e]);
    }
}

// ---------------- dinv + per-graph node counts ----------------
__global__ void k_prep(const int* __restrict__ batch, int n_nodes) {
    for (int i = blockIdx.x * blockDim.x + threadIdx.x; i < n_nodes;
         i += gridDim.x * blockDim.x) {
        g_dinv[i] = rsqrtf(g_wdeg[i] + 1.0f);
        atomicAdd(&g_cnt[batch[i]], 1.0f);
    }
}

// ---------------- fold BN params: out = A*x + B (bias folded in) ----------------
__global__ void k_bnprep(const float* b1, const float* g1, const float* be1,
                         const float* rm1, const float* rv1,
                         const float* b2, const float* g2, const float* be2,
                         const float* rm2, const float* rv2) {
    int c = threadIdx.x;
    {
        float A = g1[c] * rsqrtf(rv1[c] + BN_EPS);
        g_bnA1[c] = A;
        g_bnB1[c] = be1[c] + (b1[c] - rm1[c]) * A;
    }
    {
        float A = g2[c] * rsqrtf(rv2[c] + BN_EPS);
        g_bnA2[c] = A;
        g_bnB2[c] = be2[c] + (b2[c] - rm2[c]) * A;
    }
}

// ---------------- single-block exclusive scan of g_count -> g_rowptr/g_fill ----------------
__global__ void k_scan(int N) {
    __shared__ int warp_sums[32];
    __shared__ int s_carry;
    int t = threadIdx.x, lane = t & 31, w = t >> 5;
    if (t == 0) s_carry = 0;
    __syncthreads();
    for (int base = 0; base < N; base += 4096) {
        int i0 = base + t * 4;
        int v[4];
        #pragma unroll
        for (int j = 0; j < 4; j++) v[j] = (i0 + j < N) ? g_count[i0 + j] : 0;
        int s = v[0] + v[1] + v[2] + v[3];
        int x = s;
        #pragma unroll
        for (int o = 1; o < 32; o <<= 1) {
            int y = __shfl_up_sync(0xffffffffu, x, o);
            if (lane >= o) x += y;
        }
        if (lane == 31) warp_sums[w] = x;
        __syncthreads();
        if (w == 0) {
            int ws = warp_sums[lane];
            #pragma unroll
            for (int o = 1; o < 32; o <<= 1) {
                int y = __shfl_up_sync(0xffffffffu, ws, o);
                if (lane >= o) ws += y;
            }
            warp_sums[lane] = ws;
        }
        __syncthreads();
        int excl = x - s + (w > 0 ? warp_sums[w - 1] : 0) + s_carry;
        #pragma unroll
        for (int j = 0; j < 4; j++) {
            if (i0 + j < N) { g_rowptr[i0 + j] = excl; g_fill[i0 + j] = excl; }
            excl += v[j];
        }
        __syncthreads();
        if (t == 1023) s_carry = excl;
        __syncthreads();
    }
    if (t == 0) g_rowptr[N] = s_carry;
}

// ---------------- scatter edges into CSR slots ----------------
__global__ void k_build(const int* __restrict__ src, const int* __restrict__ dst,
                        const float* __restrict__ ew, int E) {
    for (int e = blockIdx.x * blockDim.x + threadIdx.x; e < E;
         e += gridDim.x * blockDim.x) {
        int d = dst[e];
        int p = atomicAdd(&g_fill[d], 1);
        g_csrc[p] = src[e];
        g_cw[p] = ew[e];
    }
}

// ---------------- TF32 tensor-core GEMM: C = (diag(scale)*A) @ W ----------------
// CTA 128x128, BK=32, 8 warps (2x4 grid), warp tile 64x32 (4x2 wmma m16n16k8).
// dinv row-scale folded into the A smem load; C stored directly (row-padded buffer).
__global__ __launch_bounds__(256, 2)
void k_gemm_tf32(const float* __restrict__ A, const float* __restrict__ W,
                 float* __restrict__ C, const float* __restrict__ scale,
                 int M, int K, int Nc) {
    __shared__ float As[128][36];   // [m][k], pad 32->36 (mult of 4)
    __shared__ float Bs[32][132];   // [k][n], pad 128->132

    int t = threadIdx.x;
    int warp = t >> 5;
    int wm = warp & 1;      // 0..1 -> row offset 64*wm
    int wn = warp >> 1;     // 0..3 -> col offset 32*wn
    int row0 = blockIdx.y * 128;
    int col0 = blockIdx.x * 128;

    wmma::fragment<wmma::accumulator, 16, 16, 8, float> acc[4][2];
    #pragma unroll
    for (int i = 0; i < 4; i++)
        #pragma unroll
        for (int j = 0; j < 2; j++)
            wmma::fill_fragment(acc[i][j], 0.f);

    for (int k0 = 0; k0 < K; k0 += 32) {
        // load A tile 128x32 (scaled by dinv[row]); 1024 float4 over 256 threads
        #pragma unroll
        for (int l = 0; l < 4; l++) {
            int idx = t + l * 256;
            int r = idx >> 3, c = (idx & 7) * 4;
            int gr = row0 + r;
            float4 v = make_float4(0.f, 0.f, 0.f, 0.f);
            float s = 0.f;
            if (gr < M) {
                v = *(const float4*)(A + (size_t)gr * K + k0 + c);
                s = scale[gr];
            }
            As[r][c + 0] = v.x * s;
            As[r][c + 1] = v.y * s;
            As[r][c + 2] = v.z * s;
            As[r][c + 3] = v.w * s;
        }
        // load B tile 32x128; 1024 float4 over 256 threads
        #pragma unroll
        for (int l = 0; l < 4; l++) {
            int idx = t + l * 256;
            int r = idx >> 5, c = (idx & 31) * 4;
            *(float4*)&Bs[r][c] = *(const float4*)(W + (size_t)(k0 + r) * Nc + col0 + c);
        }
        __syncthreads();

        #pragma unroll
        for (int kk = 0; kk < 32; kk += 8) {
            wmma::fragment<wmma::matrix_a, 16, 16, 8, wmma::precision::tf32, wmma::row_major> af[4];
            #pragma unroll
            for (int i = 0; i < 4; i++) {
                wmma::load_matrix_sync(af[i], &As[wm * 64 + i * 16][kk], 36);
                #pragma unroll
                for (int e = 0; e < af[i].num_elements; e++)
                    af[i].x[e] = wmma::__float_to_tf32(af[i].x[e]);
            }
            #pragma unroll
            for (int j = 0; j < 2; j++) {
                wmma::fragment<wmma::matrix_b, 16, 16, 8, wmma::precision::tf32, wmma::row_major> bf;
                wmma::load_matrix_sync(bf, &Bs[kk][wn * 32 + j * 16], 132);
                #pragma unroll
                for (int e = 0; e < bf.num_elements; e++)
                    bf.x[e] = wmma::__float_to_tf32(bf.x[e]);
                #pragma unroll
                for (int i = 0; i < 4; i++)
                    wmma::mma_sync(acc[i][j], af[i], bf, acc[i][j]);
            }
        }
        __syncthreads();
    }

    // store: C buffer is row-padded to a multiple of 128, full-tile stores are safe
    #pragma unroll
    for (int i = 0; i < 4; i++) {
        int gr = row0 + wm * 64 + i * 16;
        #pragma unroll
        for (int j = 0; j < 2; j++) {
            int gc = col0 + wn * 32 + j * 16;
            wmma::store_matrix_sync(C + (size_t)gr * Nc + gc, acc[i][j], Nc, wmma::mem_row_major);
        }
    }
}

// ---------------- CSR gather layer 1: out = relu(bnA*(dinv[d]*acc) + bnB) ----------------
// acc = h'[d] + sum_e cw[e]*h'[csrc[e]];  64 threads/node, float4 lanes.
__global__ void k_gather1(const float* __restrict__ hp, float* __restrict__ out, int N) {
    int lane = threadIdx.x & 63;
    int d = blockIdx.x * 4 + (threadIdx.x >> 6);
    if (d >= N) return;
    int c = lane * 4;
    int beg = __ldg(&g_rowptr[d]), end = __ldg(&g_rowptr[d + 1]);

    float4 acc = *(const float4*)(hp + (size_t)d * H + c);  // self-loop term
    for (int e = beg; e < end; e++) {
        int s = __ldg(&g_csrc[e]);
        float w = __ldg(&g_cw[e]);
        float4 v = *(const float4*)(hp + (size_t)s * H + c);
        acc.x += w * v.x; acc.y += w * v.y; acc.z += w * v.z; acc.w += w * v.w;
    }
    float di = g_dinv[d];
    float4 A = *(const float4*)&g_bnA1[c];
    float4 Bv = *(const float4*)&g_bnB1[c];
    float4 o;
    o.x = fmaxf(A.x * (di * acc.x) + Bv.x, 0.f);
    o.y = fmaxf(A.y * (di * acc.y) + Bv.y, 0.f);
    o.z = fmaxf(A.z * (di * acc.z) + Bv.z, 0.f);
    o.w = fmaxf(A.w * (di * acc.w) + Bv.w, 0.f);
    *(float4*)(out + (size_t)d * H + c) = o;
}

// ---------------- CSR gather layer 2 + residual + pool accumulate ----------------
__global__ void k_gather2(const float* __restrict__ hp, const float* __restrict__ res,
                          const int* __restrict__ batch, int N) {
    int lane = threadIdx.x & 63;
    int d = blockIdx.x * 4 + (threadIdx.x >> 6);
    if (d >= N) return;
    int c = lane * 4;
    int beg = __ldg(&g_rowptr[d]), end = __ldg(&g_rowptr[d + 1]);

    float4 acc = *(const float4*)(hp + (size_t)d * H + c);
    for (int e = beg; e < end; e++) {
        int s = __ldg(&g_csrc[e]);
        float w = __ldg(&g_cw[e]);
        float4 v = *(const float4*)(hp + (size_t)s * H + c);
        acc.x += w * v.x; acc.y += w * v.y; acc.z += w * v.z; acc.w += w * v.w;
    }
    float di = g_dinv[d];
    float4 A = *(const float4*)&g_bnA2[c];
    float4 Bv = *(const float4*)&g_bnB2[c];
    float4 r = *(const float4*)(res + (size_t)d * H + c);
    float vx = fmaxf(A.x * (di * acc.x) + Bv.x, 0.f) + r.x;
    float vy = fmaxf(A.y * (di * acc.y) + Bv.y, 0.f) + r.y;
    float vz = fmaxf(A.z * (di * acc.z) + Bv.z, 0.f) + r.z;
    float vw = fmaxf(A.w * (di * acc.w) + Bv.w, 0.f) + r.w;
    int b = __ldg(&batch[d]);
    red_add_v4(&g_pool[(size_t)b * H + c], vx, vy, vz, vw);
}

// ---------------- per-graph mean + write emb output ----------------
__global__ void k_emb(float* __restrict__ out, int out_size, int nb) {
    int i = blockIdx.x * blockDim.x + threadIdx.x;
    if (i < nb * H) {
        int b = i >> 8;
        float e = g_pool[i] / fmaxf(g_cnt[b], 1.0f);
        g_emb[i] = e;
        if (out_size >= nb * 2 + nb * H)
            out[nb * 2 + i] = e;
    }
}

// ---------------- classifier MLP layer: out = relu(bn(in @ W + b)) ----------------
__global__ void k_mlp(const float* __restrict__ in, const float* __restrict__ W,
                      const float* __restrict__ bb, const float* __restrict__ gg,
                      const float* __restrict__ be, const float* __restrict__ rm,
                      const float* __restrict__ rv, float* __restrict__ out,
                      int Kin, int Nout) {
    extern __shared__ float sh[];
    int b = blockIdx.x, t = threadIdx.x;
    for (int k = t; k < Kin; k += blockDim.x) sh[k] = in[(size_t)b * Kin + k];
    __syncthreads();
    if (t < Nout) {
        float acc = 0.f;
        for (int k = 0; k < Kin; k++) acc += sh[k] * W[(size_t)k * Nout + t];
        acc += bb[t];
        acc = (acc - rm[t]) * rsqrtf(rv[t] + BN_EPS) * gg[t] + be[t];
        out[(size_t)b * Nout + t] = fmaxf(acc, 0.f);
    }
}

// ---------------- final logits ----------------
__global__ void k_logits(const float* __restrict__ W, const float* __restrict__ bb,
                         float* __restrict__ out, int nb) {
    int i = blockIdx.x * blockDim.x + threadIdx.x;
    if (i < nb * 2) {
        int b = i >> 1, o = i & 1;
        float acc = bb[o];
        for (int k = 0; k < 128; k++) acc += g_z2[b * 128 + k] * W[k * 2 + o];
        out[i] = acc;
    }
}

extern "C" void kernel_launch(void* const* d_in, const int* in_sizes, int n_in,
                              void* d_out, int out_size) {
    const float* x     = (const float*)d_in[0];
    const int*   ei    = (const int*)d_in[1];
    const float* ew    = (const float*)d_in[2];
    const int*   batch = (const int*)d_in[3];
    const float* W1  = (const float*)d_in[4];
    const float* b1  = (const float*)d_in[5];
    const float* g1  = (const float*)d_in[6];
    const float* be1 = (const float*)d_in[7];
    const float* rm1 = (const float*)d_in[8];
    const float* rv1 = (const float*)d_in[9];
    const float* W2  = (const float*)d_in[10];
    const float* b2  = (const float*)d_in[11];
    const float* g2  = (const float*)d_in[12];
    const float* be2 = (const float*)d_in[13];
    const float* rm2 = (const float*)d_in[14];
    const float* rv2 = (const float*)d_in[15];
    const float* cW1  = (const float*)d_in[16];
    const float* cb1  = (const float*)d_in[17];
    const float* cg1  = (const float*)d_in[18];
    const float* cbe1 = (const float*)d_in[19];
    const float* crm1 = (const float*)d_in[20];
    const float* crv1 = (const float*)d_in[21];
    const float* cW2  = (const float*)d_in[22];
    const float* cb2  = (const float*)d_in[23];
    const float* cg2  = (const float*)d_in[24];
    const float* cbe2 = (const float*)d_in[25];
    const float* crm2 = (const float*)d_in[26];
    const float* crv2 = (const float*)d_in[27];
    const float* cW3  = (const float*)d_in[28];
    const float* cb3  = (const float*)d_in[29];

    int DIN = in_sizes[4] / H;          // 128
    int N   = in_sizes[0] / DIN;        // 100000
    int E   = in_sizes[2];              // 1600000
    int B   = (out_size % (2 + H) == 0) ? out_size / (2 + H) : BCAP;  // 256

    const int* src = ei;
    const int* dst = ei + E;

    float *bufA, *bufC, *emb, *z1, *z2, *dinv;
    cudaGetSymbolAddress((void**)&bufA, g_bufA);
    cudaGetSymbolAddress((void**)&bufC, g_bufC);
    cudaGetSymbolAddress((void**)&emb,  g_emb);
    cudaGetSymbolAddress((void**)&z1,   g_z1);
    cudaGetSymbolAddress((void**)&z2,   g_z2);
    cudaGetSymbolAddress((void**)&dinv, g_dinv);

    float* out = (float*)d_out;

    // prep: histogram, dinv, BN fold, CSR build
    int zt = 2 * N + B + B * H;
    k_zero<<<(zt + 255) / 256, 256>>>(N, B);
    k_hist<<<2048, 256>>>(dst, ew, E);
    k_prep<<<512, 256>>>(batch, N);
    k_bnprep<<<1, H>>>(b1, g1, be1, rm1, rv1, b2, g2, be2, rm2, rv2);
    k_scan<<<1, 1024>>>(N);
    k_build<<<2048, 256>>>(src, dst, ew, E);

    // layer 1
    dim3 gg((H + 127) / 128, (N + 127) / 128);
    k_gemm_tf32<<<gg, 256>>>(x, W1, bufA, dinv, N, DIN, H);
    k_gather1<<<(N + 3) / 4, 256>>>(bufA, bufC, N);

    // layer 2
    k_gemm_tf32<<<gg, 256>>>(bufC, W2, bufA, dinv, N, H, H);
    k_gather2<<<(N + 3) / 4, 256>>>(bufA, bufC, batch, N);

    // pooling + classifier
    k_emb<<<(B * H + 255) / 256, 256>>>(out, out_size, B);
    k_mlp<<<B, 256, H * sizeof(float)>>>(emb, cW1, cb1, cg1, cbe1, crm1, crv1, z1, H, 256);
    k_mlp<<<B, 256, 256 * sizeof(float)>>>(z1, cW2, cb2, cg2, cbe2, crm2, crv2, z2, 256, 128);
    k_logits<<<(B * 2 + 255) / 256, 256>>>(cW3, cb3, out, B);
}

// round 10
// speedup vs baseline: 1.3679x; 1.1035x over previous
#include <cuda_runtime.h>
#include <cuda_fp16.h>
#include <mma.h>
#include <cstddef>

using namespace nvcuda;

#define H 256
#define NCAP 100000
#define NPAD 100096      // NCAP rounded up to 128 (full-tile GEMM stores)
#define ECAP 1600000
#define BCAP 256
#define BN_EPS 1e-5f

// ---------------- scratch (static __device__, allocation-free) ----------------
__device__ __half g_bufH[(size_t)NPAD * H];  // GEMM output h' = h*dinv (fp16, row-padded)
__device__ float  g_bufC[(size_t)NCAP * H];  // h1 (post relu/bn) = residual (fp32)
__device__ float  g_wdeg[NCAP];
__device__ int    g_count[NCAP];
__device__ int    g_rowptr[NCAP + 1];
__device__ int    g_fill[NCAP];
__device__ int    g_csrc[ECAP];
__device__ float  g_cw[ECAP];
__device__ float  g_dinv[NCAP];
__device__ float  g_cnt[BCAP];
__device__ float  g_pool[BCAP * H];
__device__ float  g_emb[BCAP * H];
__device__ float  g_z1[BCAP * 256];
__device__ float  g_z2[BCAP * 128];
__device__ float  g_bnA1[H], g_bnB1[H], g_bnA2[H], g_bnB2[H];

__device__ __forceinline__ void red_add_v4(float* addr, float x, float y, float z, float w) {
    asm volatile("red.global.add.v4.f32 [%0], {%1, %2, %3, %4};"
                 :: "l"(addr), "f"(x), "f"(y), "f"(z), "f"(w) : "memory");
}

// unpack 8 halves (uint4) -> 8 floats
__device__ __forceinline__ void h8_to_f8(uint4 u, float* f) {
    const __half2* h = (const __half2*)&u;
    float2 a = __half22float2(h[0]);
    float2 b = __half22float2(h[1]);
    float2 c = __half22float2(h[2]);
    float2 d = __half22float2(h[3]);
    f[0] = a.x; f[1] = a.y; f[2] = b.x; f[3] = b.y;
    f[4] = c.x; f[5] = c.y; f[6] = d.x; f[7] = d.y;
}

// ---------------- zero accumulators ----------------
__global__ void k_zero(int n_nodes, int nb) {
    int total = 2 * n_nodes + nb + nb * H;
    for (int i = blockIdx.x * blockDim.x + threadIdx.x; i < total;
         i += gridDim.x * blockDim.x) {
        if (i < n_nodes) { g_wdeg[i] = 0.f; }
        else if (i < 2 * n_nodes) { g_count[i - n_nodes] = 0; }
        else if (i < 2 * n_nodes + nb) { g_cnt[i - 2 * n_nodes] = 0.f; }
        else { g_pool[i - 2 * n_nodes - nb] = 0.f; }
    }
}

// ---------------- histogram: count + weighted degree per dst ----------------
__global__ void k_hist(const int* __restrict__ dst, const float* __restrict__ ew, int E) {
    for (int e = blockIdx.x * blockDim.x + threadIdx.x; e < E;
         e += gridDim.x * blockDim.x) {
        int d = dst[e];
        atomicAdd(&g_count[d], 1);
        atomicAdd(&g_wdeg[d], ew[e]);
    }
}

// ---------------- dinv + per-graph node counts ----------------
__global__ void k_prep(const int* __restrict__ batch, int n_nodes) {
    for (int i = blockIdx.x * blockDim.x + threadIdx.x; i < n_nodes;
         i += gridDim.x * blockDim.x) {
        g_dinv[i] = rsqrtf(g_wdeg[i] + 1.0f);
        atomicAdd(&g_cnt[batch[i]], 1.0f);
    }
}

// ---------------- fold BN params ----------------
__global__ void k_bnprep(const float* b1, const float* g1, const float* be1,
                         const float* rm1, const float* rv1,
                         const float* b2, const float* g2, const float* be2,
                         const float* rm2, const float* rv2) {
    int c = threadIdx.x;
    {
        float A = g1[c] * rsqrtf(rv1[c] + BN_EPS);
        g_bnA1[c] = A;
        g_bnB1[c] = be1[c] + (b1[c] - rm1[c]) * A;
    }
    {
        float A = g2[c] * rsqrtf(rv2[c] + BN_EPS);
        g_bnA2[c] = A;
        g_bnB2[c] = be2[c] + (b2[c] - rm2[c]) * A;
    }
}

// ---------------- single-block exclusive scan of g_count ----------------
__global__ void k_scan(int N) {
    __shared__ int warp_sums[32];
    __shared__ int s_carry;
    int t = threadIdx.x, lane = t & 31, w = t >> 5;
    if (t == 0) s_carry = 0;
    __syncthreads();
    for (int base = 0; base < N; base += 4096) {
        int i0 = base + t * 4;
        int v[4];
        #pragma unroll
        for (int j = 0; j < 4; j++) v[j] = (i0 + j < N) ? g_count[i0 + j] : 0;
        int s = v[0] + v[1] + v[2] + v[3];
        int x = s;
        #pragma unroll
        for (int o = 1; o < 32; o <<= 1) {
            int y = __shfl_up_sync(0xffffffffu, x, o);
            if (lane >= o) x += y;
        }
        if (lane == 31) warp_sums[w] = x;
        __syncthreads();
        if (w == 0) {
            int ws = warp_sums[lane];
            #pragma unroll
            for (int o = 1; o < 32; o <<= 1) {
                int y = __shfl_up_sync(0xffffffffu, ws, o);
                if (lane >= o) ws += y;
            }
            warp_sums[lane] = ws;
        }
        __syncthreads();
        int excl = x - s + (w > 0 ? warp_sums[w - 1] : 0) + s_carry;
        #pragma unroll
        for (int j = 0; j < 4; j++) {
            if (i0 + j < N) { g_rowptr[i0 + j] = excl; g_fill[i0 + j] = excl; }
            excl += v[j];
        }
        __syncthreads();
        if (t == 1023) s_carry = excl;
        __syncthreads();
    }
    if (t == 0) g_rowptr[N] = s_carry;
}

// ---------------- scatter edges into CSR slots ----------------
__global__ void k_build(const int* __restrict__ src, const int* __restrict__ dst,
                        const float* __restrict__ ew, int E) {
    for (int e = blockIdx.x * blockDim.x + threadIdx.x; e < E;
         e += gridDim.x * blockDim.x) {
        int d = dst[e];
        int p = atomicAdd(&g_fill[d], 1);
        g_csrc[p] = src[e];
        g_cw[p] = ew[e];
    }
}

// ---------------- TF32 GEMM: Ch = fp16( (diag(scale)*A) @ W ) ----------------
// CTA 128x128, BK=32, 8 warps, warp tile 64x32 (4x2 wmma m16n16k8).
__global__ __launch_bounds__(256, 2)
void k_gemm_tf32(const float* __restrict__ A, const float* __restrict__ W,
                 __half* __restrict__ Ch, const float* __restrict__ scale,
                 int M, int K, int Nc) {
    __shared__ float As[128][36];   // [m][k]
    __shared__ float Bs[32][132];   // [k][n]
    __shared__ float St[8][16][20]; // per-warp 16x16 staging (pad 16->20)

    int t = threadIdx.x;
    int warp = t >> 5;
    int lane = t & 31;
    int wm = warp & 1;
    int wn = warp >> 1;
    int row0 = blockIdx.y * 128;
    int col0 = blockIdx.x * 128;

    wmma::fragment<wmma::accumulator, 16, 16, 8, float> acc[4][2];
    #pragma unroll
    for (int i = 0; i < 4; i++)
        #pragma unroll
        for (int j = 0; j < 2; j++)
            wmma::fill_fragment(acc[i][j], 0.f);

    for (int k0 = 0; k0 < K; k0 += 32) {
        #pragma unroll
        for (int l = 0; l < 4; l++) {
            int idx = t + l * 256;
            int r = idx >> 3, c = (idx & 7) * 4;
            int gr = row0 + r;
            float4 v = make_float4(0.f, 0.f, 0.f, 0.f);
            float s = 0.f;
            if (gr < M) {
                v = *(const float4*)(A + (size_t)gr * K + k0 + c);
                s = scale[gr];
            }
            As[r][c + 0] = v.x * s;
            As[r][c + 1] = v.y * s;
            As[r][c + 2] = v.z * s;
            As[r][c + 3] = v.w * s;
        }
        #pragma unroll
        for (int l = 0; l < 4; l++) {
            int idx = t + l * 256;
            int r = idx >> 5, c = (idx & 31) * 4;
            *(float4*)&Bs[r][c] = *(const float4*)(W + (size_t)(k0 + r) * Nc + col0 + c);
        }
        __syncthreads();

        #pragma unroll
        for (int kk = 0; kk < 32; kk += 8) {
            wmma::fragment<wmma::matrix_a, 16, 16, 8, wmma::precision::tf32, wmma::row_major> af[4];
            #pragma unroll
            for (int i = 0; i < 4; i++) {
                wmma::load_matrix_sync(af[i], &As[wm * 64 + i * 16][kk], 36);
                #pragma unroll
                for (int e = 0; e < af[i].num_elements; e++)
                    af[i].x[e] = wmma::__float_to_tf32(af[i].x[e]);
            }
            #pragma unroll
            for (int j = 0; j < 2; j++) {
                wmma::fragment<wmma::matrix_b, 16, 16, 8, wmma::precision::tf32, wmma::row_major> bf;
                wmma::load_matrix_sync(bf, &Bs[kk][wn * 32 + j * 16], 132);
                #pragma unroll
                for (int e = 0; e < bf.num_elements; e++)
                    bf.x[e] = wmma::__float_to_tf32(bf.x[e]);
                #pragma unroll
                for (int i = 0; i < 4; i++)
                    wmma::mma_sync(acc[i][j], af[i], bf, acc[i][j]);
            }
        }
        __syncthreads();
    }

    // epilogue: stage each 16x16 tile in smem, convert to fp16, store 16B/lane.
    int sr = lane >> 1, sc = (lane & 1) * 8;
    #pragma unroll
    for (int i = 0; i < 4; i++) {
        int gr = row0 + wm * 64 + i * 16;
        #pragma unroll
        for (int j = 0; j < 2; j++) {
            int gc = col0 + wn * 32 + j * 16;
            wmma::store_matrix_sync(&St[warp][0][0], acc[i][j], 20, wmma::mem_row_major);
            __syncwarp();
            const float* p = &St[warp][sr][sc];
            __half2 h[4];
            h[0] = __floats2half2_rn(p[0], p[1]);
            h[1] = __floats2half2_rn(p[2], p[3]);
            h[2] = __floats2half2_rn(p[4], p[5]);
            h[3] = __floats2half2_rn(p[6], p[7]);
            *(uint4*)(Ch + (size_t)(gr + sr) * Nc + gc + sc) = *(uint4*)h;
            __syncwarp();
        }
    }
}

// ---------------- CSR gather core (warp per node, 8 ch/lane, fp16 h') ----------------
__device__ __forceinline__ void gather_acc_h(const __half* __restrict__ hp, int d, int c,
                                             float* acc) {
    int beg = __ldg(&g_rowptr[d]), end = __ldg(&g_rowptr[d + 1]);
    // self-loop term
    h8_to_f8(*(const uint4*)(hp + (size_t)d * H + c), acc);
    int e = beg;
    for (; e + 2 <= end; e += 2) {
        int s0 = __ldg(&g_csrc[e]),     s1 = __ldg(&g_csrc[e + 1]);
        float w0 = __ldg(&g_cw[e]),     w1 = __ldg(&g_cw[e + 1]);
        uint4 u0 = *(const uint4*)(hp + (size_t)s0 * H + c);
        uint4 u1 = *(const uint4*)(hp + (size_t)s1 * H + c);
        float f0[8], f1[8];
        h8_to_f8(u0, f0);
        h8_to_f8(u1, f1);
        #pragma unroll
        for (int q = 0; q < 8; q++) acc[q] += w0 * f0[q] + w1 * f1[q];
    }
    if (e < end) {
        int s = __ldg(&g_csrc[e]);
        float w = __ldg(&g_cw[e]);
        uint4 u = *(const uint4*)(hp + (size_t)s * H + c);
        float f[8];
        h8_to_f8(u, f);
        #pragma unroll
        for (int q = 0; q < 8; q++) acc[q] += w * f[q];
    }
}

// ---------------- gather layer 1: bufC = relu(bnA*(dinv[d]*acc) + bnB) ----------------
__global__ void k_gather1(const __half* __restrict__ hp, float* __restrict__ out, int N) {
    int lane = threadIdx.x & 31;
    int d = blockIdx.x * 8 + (threadIdx.x >> 5);
    if (d >= N) return;
    int c = lane * 8;
    float acc[8];
    gather_acc_h(hp, d, c, acc);
    float di = g_dinv[d];
    float4 A0 = *(const float4*)&g_bnA1[c], A1 = *(const float4*)&g_bnA1[c + 4];
    float4 B0 = *(const float4*)&g_bnB1[c], B1 = *(const float4*)&g_bnB1[c + 4];
    float4 o0, o1;
    o0.x = fmaxf(A0.x * (di * acc[0]) + B0.x, 0.f);
    o0.y = fmaxf(A0.y * (di * acc[1]) + B0.y, 0.f);
    o0.z = fmaxf(A0.z * (di * acc[2]) + B0.z, 0.f);
    o0.w = fmaxf(A0.w * (di * acc[3]) + B0.w, 0.f);
    o1.x = fmaxf(A1.x * (di * acc[4]) + B1.x, 0.f);
    o1.y = fmaxf(A1.y * (di * acc[5]) + B1.y, 0.f);
    o1.z = fmaxf(A1.z * (di * acc[6]) + B1.z, 0.f);
    o1.w = fmaxf(A1.w * (di * acc[7]) + B1.w, 0.f);
    *(float4*)(out + (size_t)d * H + c) = o0;
    *(float4*)(out + (size_t)d * H + c + 4) = o1;
}

// ---------------- gather layer 2 + residual + pool accumulate ----------------
__global__ void k_gather2(const __half* __restrict__ hp, const float* __restrict__ res,
                          const int* __restrict__ batch, int N) {
    int lane = threadIdx.x & 31;
    int d = blockIdx.x * 8 + (threadIdx.x >> 5);
    if (d >= N) return;
    int c = lane * 8;
    float acc[8];
    gather_acc_h(hp, d, c, acc);
    float di = g_dinv[d];
    float4 A0 = *(const float4*)&g_bnA2[c], A1 = *(const float4*)&g_bnA2[c + 4];
    float4 B0 = *(const float4*)&g_bnB2[c], B1 = *(const float4*)&g_bnB2[c + 4];
    float4 r0 = *(const float4*)(res + (size_t)d * H + c);
    float4 r1 = *(const float4*)(res + (size_t)d * H + c + 4);
    float v0 = fmaxf(A0.x * (di * acc[0]) + B0.x, 0.f) + r0.x;
    float v1 = fmaxf(A0.y * (di * acc[1]) + B0.y, 0.f) + r0.y;
    float v2 = fmaxf(A0.z * (di * acc[2]) + B0.z, 0.f) + r0.z;
    float v3 = fmaxf(A0.w * (di * acc[3]) + B0.w, 0.f) + r0.w;
    float v4 = fmaxf(A1.x * (di * acc[4]) + B1.x, 0.f) + r1.x;
    float v5 = fmaxf(A1.y * (di * acc[5]) + B1.y, 0.f) + r1.y;
    float v6 = fmaxf(A1.z * (di * acc[6]) + B1.z, 0.f) + r1.z;
    float v7 = fmaxf(A1.w * (di * acc[7]) + B1.w, 0.f) + r1.w;
    int b = __ldg(&batch[d]);
    red_add_v4(&g_pool[(size_t)b * H + c], v0, v1, v2, v3);
    red_add_v4(&g_pool[(size_t)b * H + c + 4], v4, v5, v6, v7);
}

// ---------------- per-graph mean + write emb output ----------------
__global__ void k_emb(float* __restrict__ out, int out_size, int nb) {
    int i = blockIdx.x * blockDim.x + threadIdx.x;
    if (i < nb * H) {
        int b = i >> 8;
        float e = g_pool[i] / fmaxf(g_cnt[b], 1.0f);
        g_emb[i] = e;
        if (out_size >= nb * 2 + nb * H)
            out[nb * 2 + i] = e;
    }
}

// ---------------- classifier MLP layer ----------------
__global__ void k_mlp(const float* __restrict__ in, const float* __restrict__ W,
                      const float* __restrict__ bb, const float* __restrict__ gg,
                      const float* __restrict__ be, const float* __restrict__ rm,
                      const float* __restrict__ rv, float* __restrict__ out,
                      int Kin, int Nout) {
    extern __shared__ float sh[];
    int b = blockIdx.x, t = threadIdx.x;
    for (int k = t; k < Kin; k += blockDim.x) sh[k] = in[(size_t)b * Kin + k];
    __syncthreads();
    if (t < Nout) {
        float acc = 0.f;
        for (int k = 0; k < Kin; k++) acc += sh[k] * W[(size_t)k * Nout + t];
        acc += bb[t];
        acc = (acc - rm[t]) * rsqrtf(rv[t] + BN_EPS) * gg[t] + be[t];
        out[(size_t)b * Nout + t] = fmaxf(acc, 0.f);
    }
}

// ---------------- final logits ----------------
__global__ void k_logits(const float* __restrict__ W, const float* __restrict__ bb,
                         float* __restrict__ out, int nb) {
    int i = blockIdx.x * blockDim.x + threadIdx.x;
    if (i < nb * 2) {
        int b = i >> 1, o = i & 1;
        float acc = bb[o];
        for (int k = 0; k < 128; k++) acc += g_z2[b * 128 + k] * W[k * 2 + o];
        out[i] = acc;
    }
}

extern "C" void kernel_launch(void* const* d_in, const int* in_sizes, int n_in,
                              void* d_out, int out_size) {
    const float* x     = (const float*)d_in[0];
    const int*   ei    = (const int*)d_in[1];
    const float* ew    = (const float*)d_in[2];
    const int*   batch = (const int*)d_in[3];
    const float* W1  = (const float*)d_in[4];
    const float* b1  = (const float*)d_in[5];
    const float* g1  = (const float*)d_in[6];
    const float* be1 = (const float*)d_in[7];
    const float* rm1 = (const float*)d_in[8];
    const float* rv1 = (const float*)d_in[9];
    const float* W2  = (const float*)d_in[10];
    const float* b2  = (const float*)d_in[11];
    const float* g2  = (const float*)d_in[12];
    const float* be2 = (const float*)d_in[13];
    const float* rm2 = (const float*)d_in[14];
    const float* rv2 = (const float*)d_in[15];
    const float* cW1  = (const float*)d_in[16];
    const float* cb1  = (const float*)d_in[17];
    const float* cg1  = (const float*)d_in[18];
    const float* cbe1 = (const float*)d_in[19];
    const float* crm1 = (const float*)d_in[20];
    const float* crv1 = (const float*)d_in[21];
    const float* cW2  = (const float*)d_in[22];
    const float* cb2  = (const float*)d_in[23];
    const float* cg2  = (const float*)d_in[24];
    const float* cbe2 = (const float*)d_in[25];
    const float* crm2 = (const float*)d_in[26];
    const float* crv2 = (const float*)d_in[27];
    const float* cW3  = (const float*)d_in[28];
    const float* cb3  = (const float*)d_in[29];

    int DIN = in_sizes[4] / H;          // 128
    int N   = in_sizes[0] / DIN;        // 100000
    int E   = in_sizes[2];              // 1600000
    int B   = (out_size % (2 + H) == 0) ? out_size / (2 + H) : BCAP;  // 256

    const int* src = ei;
    const int* dst = ei + E;

    __half* bufH;
    float *bufC, *emb, *z1, *z2, *dinv;
    cudaGetSymbolAddress((void**)&bufH, g_bufH);
    cudaGetSymbolAddress((void**)&bufC, g_bufC);
    cudaGetSymbolAddress((void**)&emb,  g_emb);
    cudaGetSymbolAddress((void**)&z1,   g_z1);
    cudaGetSymbolAddress((void**)&z2,   g_z2);
    cudaGetSymbolAddress((void**)&dinv, g_dinv);

    float* out = (float*)d_out;

    // prep: histogram, dinv, BN fold, CSR build
    int zt = 2 * N + B + B * H;
    k_zero<<<(zt + 255) / 256, 256>>>(N, B);
    k_hist<<<2048, 256>>>(dst, ew, E);
    k_prep<<<512, 256>>>(batch, N);
    k_bnprep<<<1, H>>>(b1, g1, be1, rm1, rv1, b2, g2, be2, rm2, rv2);
    k_scan<<<1, 1024>>>(N);
    k_build<<<2048, 256>>>(src, dst, ew, E);

    // layer 1
    dim3 gg((H + 127) / 128, (N + 127) / 128);
    k_gemm_tf32<<<gg, 256>>>(x, W1, bufH, dinv, N, DIN, H);
    k_gather1<<<(N + 7) / 8, 256>>>(bufH, bufC, N);

    // layer 2
    k_gemm_tf32<<<gg, 256>>>(bufC, W2, bufH, dinv, N, H, H);
    k_gather2<<<(N + 7) / 8, 256>>>(bufH, bufC, batch, N);

    // pooling + classifier
    k_emb<<<(B * H + 255) / 256, 256>>>(out, out_size, B);
    k_mlp<<<B, 256, H * sizeof(float)>>>(emb, cW1, cb1, cg1, cbe1, crm1, crv1, z1, H, 256);
    k_mlp<<<B, 256, 256 * sizeof(float)>>>(z1, cW2, cb2, cg2, cbe2, crm2, crv2, z2, 256, 128);
    k_logits<<<(B * 2 + 255) / 256, 256>>>(cW3, cb3, out, B);
}

// round 12
// speedup vs baseline: 1.7435x; 1.2746x over previous
#include <cuda_runtime.h>
#include <cuda_fp16.h>
#include <mma.h>
#include <cstddef>

using namespace nvcuda;

#define H 256
#define NCAP 100000
#define NPAD 100096      // NCAP rounded up to 128 (full-tile GEMM stores)
#define ECAP 1600000
#define BCAP 256
#define BN_EPS 1e-5f

// ---------------- scratch (static __device__, allocation-free) ----------------
__device__ __half g_bufH[(size_t)NPAD * H];   // GEMM output h' = h*dinv (fp16)
__device__ __half g_bufCh[(size_t)NPAD * H];  // h1 in fp16 (GEMM2 A input)
__device__ __half g_xh[(size_t)NPAD * 128];   // x in fp16
__device__ __half g_w1h[128 * H];
__device__ __half g_w2h[H * H];
__device__ float  g_bufC[(size_t)NCAP * H];   // h1 fp32 (residual)
__device__ float  g_wdeg[NCAP];
__device__ int    g_count[NCAP];
__device__ int    g_rowptr[NCAP + 1];
__device__ int    g_fill[NCAP];
__device__ int    g_csrc[ECAP];
__device__ float  g_cw[ECAP];
__device__ float  g_dinv[NCAP];
__device__ float  g_cnt[BCAP];
__device__ float  g_pool[BCAP * H];
__device__ float  g_emb[BCAP * H];
__device__ float  g_z1[BCAP * 256];
__device__ float  g_z2[BCAP * 128];
__device__ float  g_bnA1[H], g_bnB1[H], g_bnA2[H], g_bnB2[H];

__device__ __forceinline__ void red_add_v4(float* addr, float x, float y, float z, float w) {
    asm volatile("red.global.add.v4.f32 [%0], {%1, %2, %3, %4};"
                 :: "l"(addr), "f"(x), "f"(y), "f"(z), "f"(w) : "memory");
}

__device__ __forceinline__ void h8_to_f8(uint4 u, float* f) {
    const __half2* h = (const __half2*)&u;
    float2 a = __half22float2(h[0]);
    float2 b = __half22float2(h[1]);
    float2 c = __half22float2(h[2]);
    float2 d = __half22float2(h[3]);
    f[0] = a.x; f[1] = a.y; f[2] = b.x; f[3] = b.y;
    f[4] = c.x; f[5] = c.y; f[6] = d.x; f[7] = d.y;
}

// ---------------- zero accumulators ----------------
__global__ void k_zero(int n_nodes, int nb) {
    int total = 2 * n_nodes + nb + nb * H;
    for (int i = blockIdx.x * blockDim.x + threadIdx.x; i < total;
         i += gridDim.x * blockDim.x) {
        if (i < n_nodes) { g_wdeg[i] = 0.f; }
        else if (i < 2 * n_nodes) { g_count[i - n_nodes] = 0; }
        else if (i < 2 * n_nodes + nb) { g_cnt[i - 2 * n_nodes] = 0.f; }
        else { g_pool[i - 2 * n_nodes - nb] = 0.f; }
    }
}

// ---------------- fp32 -> fp16 conversions (x, W1, W2) ----------------
__global__ void k_cvt(const float* __restrict__ x, const float* __restrict__ W1,
                      const float* __restrict__ W2, int nx, int nw1, int nw2) {
    int total = nx + nw1 + nw2;
    for (int i = blockIdx.x * blockDim.x + threadIdx.x; i < total;
         i += gridDim.x * blockDim.x) {
        if (i < nx) g_xh[i] = __float2half_rn(x[i]);
        else if (i < nx + nw1) g_w1h[i - nx] = __float2half_rn(W1[i - nx]);
        else g_w2h[i - nx - nw1] = __float2half_rn(W2[i - nx - nw1]);
    }
}

// ---------------- histogram: count + weighted degree per dst ----------------
__global__ void k_hist(const int* __restrict__ dst, const float* __restrict__ ew, int E) {
    for (int e = blockIdx.x * blockDim.x + threadIdx.x; e < E;
         e += gridDim.x * blockDim.x) {
        int d = dst[e];
        atomicAdd(&g_count[d], 1);
        atomicAdd(&g_wdeg[d], ew[e]);
    }
}

// ---------------- dinv + per-graph node counts ----------------
__global__ void k_prep(const int* __restrict__ batch, int n_nodes) {
    for (int i = blockIdx.x * blockDim.x + threadIdx.x; i < n_nodes;
         i += gridDim.x * blockDim.x) {
        g_dinv[i] = rsqrtf(g_wdeg[i] + 1.0f);
        atomicAdd(&g_cnt[batch[i]], 1.0f);
    }
}

// ---------------- fold BN params ----------------
__global__ void k_bnprep(const float* b1, const float* g1, const float* be1,
                         const float* rm1, const float* rv1,
                         const float* b2, const float* g2, const float* be2,
                         const float* rm2, const float* rv2) {
    int c = threadIdx.x;
    {
        float A = g1[c] * rsqrtf(rv1[c] + BN_EPS);
        g_bnA1[c] = A;
        g_bnB1[c] = be1[c] + (b1[c] - rm1[c]) * A;
    }
    {
        float A = g2[c] * rsqrtf(rv2[c] + BN_EPS);
        g_bnA2[c] = A;
        g_bnB2[c] = be2[c] + (b2[c] - rm2[c]) * A;
    }
}

// ---------------- single-block exclusive scan of g_count ----------------
__global__ void k_scan(int N) {
    __shared__ int warp_sums[32];
    __shared__ int s_carry;
    int t = threadIdx.x, lane = t & 31, w = t >> 5;
    if (t == 0) s_carry = 0;
    __syncthreads();
    for (int base = 0; base < N; base += 4096) {
        int i0 = base + t * 4;
        int v[4];
        #pragma unroll
        for (int j = 0; j < 4; j++) v[j] = (i0 + j < N) ? g_count[i0 + j] : 0;
        int s = v[0] + v[1] + v[2] + v[3];
        int x = s;
        #pragma unroll
        for (int o = 1; o < 32; o <<= 1) {
            int y = __shfl_up_sync(0xffffffffu, x, o);
            if (lane >= o) x += y;
        }
        if (lane == 31) warp_sums[w] = x;
        __syncthreads();
        if (w == 0) {
            int ws = warp_sums[lane];
            #pragma unroll
            for (int o = 1; o < 32; o <<= 1) {
                int y = __shfl_up_sync(0xffffffffu, ws, o);
                if (lane >= o) ws += y;
            }
            warp_sums[lane] = ws;
        }
        __syncthreads();
        int excl = x - s + (w > 0 ? warp_sums[w - 1] : 0) + s_carry;
        #pragma unroll
        for (int j = 0; j < 4; j++) {
            if (i0 + j < N) { g_rowptr[i0 + j] = excl; g_fill[i0 + j] = excl; }
            excl += v[j];
        }
        __syncthreads();
        if (t == 1023) s_carry = excl;
        __syncthreads();
    }
    if (t == 0) g_rowptr[N] = s_carry;
}

// ---------------- scatter edges into CSR slots ----------------
__global__ void k_build(const int* __restrict__ src, const int* __restrict__ dst,
                        const float* __restrict__ ew, int E) {
    for (int e = blockIdx.x * blockDim.x + threadIdx.x; e < E;
         e += gridDim.x * blockDim.x) {
        int d = dst[e];
        int p = atomicAdd(&g_fill[d], 1);
        g_csrc[p] = src[e];
        g_cw[p] = ew[e];
    }
}

// ---------------- fp16 tensor GEMM: Ch = fp16( (diag(scale)*A) @ W ) ----------------
// CTA 128x128, BK=32, 8 warps, warp tile 64x32 (4x2 wmma m16n16k16), fp32 accum.
__global__ __launch_bounds__(256, 2)
void k_gemm_f16(const __half* __restrict__ A, const __half* __restrict__ W,
                __half* __restrict__ Ch, const float* __restrict__ scale,
                int M, int K, int Nc) {
    __shared__ __half As[128][48];   // [m][k], pad 32->48 (96B rows, 16B aligned)
    __shared__ __half Bs[32][136];   // [k][n], pad 128->136 (272B rows)
    __shared__ float  St[8][16][20]; // per-warp 16x16 fp32 staging

    int t = threadIdx.x;
    int warp = t >> 5;
    int lane = t & 31;
    int wm = warp & 1;
    int wn = warp >> 1;
    int row0 = blockIdx.y * 128;
    int col0 = blockIdx.x * 128;

    wmma::fragment<wmma::accumulator, 16, 16, 16, float> acc[4][2];
    #pragma unroll
    for (int i = 0; i < 4; i++)
        #pragma unroll
        for (int j = 0; j < 2; j++)
            wmma::fill_fragment(acc[i][j], 0.f);

    for (int k0 = 0; k0 < K; k0 += 32) {
        // A tile 128x32 halves: 512 uint4, 2 per thread; scale by dinv[row]
        #pragma unroll
        for (int l = 0; l < 2; l++) {
            int idx = t + l * 256;
            int r = idx >> 2, c = (idx & 3) * 8;
            int gr = row0 + r;
            uint4 u = make_uint4(0, 0, 0, 0);
            float s = 0.f;
            if (gr < M) {
                u = *(const uint4*)(A + (size_t)gr * K + k0 + c);
                s = scale[gr];
            }
            __half2 hs = __float2half2_rn(s);
            __half2* h = (__half2*)&u;
            h[0] = __hmul2(h[0], hs);
            h[1] = __hmul2(h[1], hs);
            h[2] = __hmul2(h[2], hs);
            h[3] = __hmul2(h[3], hs);
            *(uint4*)&As[r][c] = u;
        }
        // B tile 32x128 halves: 512 uint4, 2 per thread
        #pragma unroll
        for (int l = 0; l < 2; l++) {
            int idx = t + l * 256;
            int r = idx >> 4, c = (idx & 15) * 8;
            *(uint4*)&Bs[r][c] = *(const uint4*)(W + (size_t)(k0 + r) * Nc + col0 + c);
        }
        __syncthreads();

        #pragma unroll
        for (int kk = 0; kk < 32; kk += 16) {
            wmma::fragment<wmma::matrix_a, 16, 16, 16, __half, wmma::row_major> af[4];
            #pragma unroll
            for (int i = 0; i < 4; i++)
                wmma::load_matrix_sync(af[i], &As[wm * 64 + i * 16][kk], 48);
            #pragma unroll
            for (int j = 0; j < 2; j++) {
                wmma::fragment<wmma::matrix_b, 16, 16, 16, __half, wmma::row_major> bf;
                wmma::load_matrix_sync(bf, &Bs[kk][wn * 32 + j * 16], 136);
                #pragma unroll
                for (int i = 0; i < 4; i++)
                    wmma::mma_sync(acc[i][j], af[i], bf, acc[i][j]);
            }
        }
        __syncthreads();
    }

    // epilogue: stage fp32 tile in smem, convert to fp16, 16B/lane stores
    int sr = lane >> 1, sc = (lane & 1) * 8;
    #pragma unroll
    for (int i = 0; i < 4; i++) {
        int gr = row0 + wm * 64 + i * 16;
        #pragma unroll
        for (int j = 0; j < 2; j++) {
            int gc = col0 + wn * 32 + j * 16;
            wmma::store_matrix_sync(&St[warp][0][0], acc[i][j], 20, wmma::mem_row_major);
            __syncwarp();
            const float* p = &St[warp][sr][sc];
            __half2 h[4];
            h[0] = __floats2half2_rn(p[0], p[1]);
            h[1] = __floats2half2_rn(p[2], p[3]);
            h[2] = __floats2half2_rn(p[4], p[5]);
            h[3] = __floats2half2_rn(p[6], p[7]);
            *(uint4*)(Ch + (size_t)(gr + sr) * Nc + gc + sc) = *(uint4*)h;
            __syncwarp();
        }
    }
}

// ---------------- CSR gather core (warp per node, 8 ch/lane, fp16 h') ----------------
__device__ __forceinline__ void gather_acc_h(const __half* __restrict__ hp, int d, int c,
                                             float* acc) {
    int beg = __ldg(&g_rowptr[d]), end = __ldg(&g_rowptr[d + 1]);
    h8_to_f8(*(const uint4*)(hp + (size_t)d * H + c), acc);  // self-loop term
    int e = beg;
    for (; e + 2 <= end; e += 2) {
        int s0 = __ldg(&g_csrc[e]),     s1 = __ldg(&g_csrc[e + 1]);
        float w0 = __ldg(&g_cw[e]),     w1 = __ldg(&g_cw[e + 1]);
        uint4 u0 = *(const uint4*)(hp + (size_t)s0 * H + c);
        uint4 u1 = *(const uint4*)(hp + (size_t)s1 * H + c);
        float f0[8], f1[8];
        h8_to_f8(u0, f0);
        h8_to_f8(u1, f1);
        #pragma unroll
        for (int q = 0; q < 8; q++) acc[q] += w0 * f0[q] + w1 * f1[q];
    }
    if (e < end) {
        int s = __ldg(&g_csrc[e]);
        float w = __ldg(&g_cw[e]);
        uint4 u = *(const uint4*)(hp + (size_t)s * H + c);
        float f[8];
        h8_to_f8(u, f);
        #pragma unroll
        for (int q = 0; q < 8; q++) acc[q] += w * f[q];
    }
}

// ---------------- gather layer 1: fp32 residual out + fp16 GEMM2 input ----------------
__global__ void k_gather1(const __half* __restrict__ hp, float* __restrict__ out,
                          __half* __restrict__ outh, int N) {
    int lane = threadIdx.x & 31;
    int d = blockIdx.x * 8 + (threadIdx.x >> 5);
    if (d >= N) return;
    int c = lane * 8;
    float acc[8];
    gather_acc_h(hp, d, c, acc);
    float di = g_dinv[d];
    float4 A0 = *(const float4*)&g_bnA1[c], A1 = *(const float4*)&g_bnA1[c + 4];
    float4 B0 = *(const float4*)&g_bnB1[c], B1 = *(const float4*)&g_bnB1[c + 4];
    float o[8];
    o[0] = fmaxf(A0.x * (di * acc[0]) + B0.x, 0.f);
    o[1] = fmaxf(A0.y * (di * acc[1]) + B0.y, 0.f);
    o[2] = fmaxf(A0.z * (di * acc[2]) + B0.z, 0.f);
    o[3] = fmaxf(A0.w * (di * acc[3]) + B0.w, 0.f);
    o[4] = fmaxf(A1.x * (di * acc[4]) + B1.x, 0.f);
    o[5] = fmaxf(A1.y * (di * acc[5]) + B1.y, 0.f);
    o[6] = fmaxf(A1.z * (di * acc[6]) + B1.z, 0.f);
    o[7] = fmaxf(A1.w * (di * acc[7]) + B1.w, 0.f);
    *(float4*)(out + (size_t)d * H + c) = make_float4(o[0], o[1], o[2], o[3]);
    *(float4*)(out + (size_t)d * H + c + 4) = make_float4(o[4], o[5], o[6], o[7]);
    __half2 h[4];
    h[0] = __floats2half2_rn(o[0], o[1]);
    h[1] = __floats2half2_rn(o[2], o[3]);
    h[2] = __floats2half2_rn(o[4], o[5]);
    h[3] = __floats2half2_rn(o[6], o[7]);
    *(uint4*)(outh + (size_t)d * H + c) = *(uint4*)h;
}

// ---------------- gather layer 2 + residual + pool accumulate ----------------
__global__ void k_gather2(const __half* __restrict__ hp, const float* __restrict__ res,
                          const int* __restrict__ batch, int N) {
    int lane = threadIdx.x & 31;
    int d = blockIdx.x * 8 + (threadIdx.x >> 5);
    if (d >= N) return;
    int c = lane * 8;
    float acc[8];
    gather_acc_h(hp, d, c, acc);
    float di = g_dinv[d];
    float4 A0 = *(const float4*)&g_bnA2[c], A1 = *(const float4*)&g_bnA2[c + 4];
    float4 B0 = *(const float4*)&g_bnB2[c], B1 = *(const float4*)&g_bnB2[c + 4];
    float4 r0 = *(const float4*)(res + (size_t)d * H + c);
    float4 r1 = *(const float4*)(res + (size_t)d * H + c + 4);
    float v0 = fmaxf(A0.x * (di * acc[0]) + B0.x, 0.f) + r0.x;
    float v1 = fmaxf(A0.y * (di * acc[1]) + B0.y, 0.f) + r0.y;
    float v2 = fmaxf(A0.z * (di * acc[2]) + B0.z, 0.f) + r0.z;
    float v3 = fmaxf(A0.w * (di * acc[3]) + B0.w, 0.f) + r0.w;
    float v4 = fmaxf(A1.x * (di * acc[4]) + B1.x, 0.f) + r1.x;
    float v5 = fmaxf(A1.y * (di * acc[5]) + B1.y, 0.f) + r1.y;
    float v6 = fmaxf(A1.z * (di * acc[6]) + B1.z, 0.f) + r1.z;
    float v7 = fmaxf(A1.w * (di * acc[7]) + B1.w, 0.f) + r1.w;
    int b = __ldg(&batch[d]);
    red_add_v4(&g_pool[(size_t)b * H + c], v0, v1, v2, v3);
    red_add_v4(&g_pool[(size_t)b * H + c + 4], v4, v5, v6, v7);
}

// ---------------- per-graph mean + write emb output ----------------
__global__ void k_emb(float* __restrict__ out, int out_size, int nb) {
    int i = blockIdx.x * blockDim.x + threadIdx.x;
    if (i < nb * H) {
        int b = i >> 8;
        float e = g_pool[i] / fmaxf(g_cnt[b], 1.0f);
        g_emb[i] = e;
        if (out_size >= nb * 2 + nb * H)
            out[nb * 2 + i] = e;
    }
}

// ---------------- classifier MLP layer ----------------
__global__ void k_mlp(const float* __restrict__ in, const float* __restrict__ W,
                      const float* __restrict__ bb, const float* __restrict__ gg,
                      const float* __restrict__ be, const float* __restrict__ rm,
                      const float* __restrict__ rv, float* __restrict__ out,
                      int Kin, int Nout) {
    extern __shared__ float sh[];
    int b = blockIdx.x, t = threadIdx.x;
    for (int k = t; k < Kin; k += blockDim.x) sh[k] = in[(size_t)b * Kin + k];
    __syncthreads();
    if (t < Nout) {
        float acc = 0.f;
        for (int k = 0; k < Kin; k++) acc += sh[k] * W[(size_t)k * Nout + t];
        acc += bb[t];
        acc = (acc - rm[t]) * rsqrtf(rv[t] + BN_EPS) * gg[t] + be[t];
        out[(size_t)b * Nout + t] = fmaxf(acc, 0.f);
    }
}

// ---------------- final logits ----------------
__global__ void k_logits(const float* __restrict__ W, const float* __restrict__ bb,
                         float* __restrict__ out, int nb) {
    int i = blockIdx.x * blockDim.x + threadIdx.x;
    if (i < nb * 2) {
        int b = i >> 1, o = i & 1;
        float acc = bb[o];
        for (int k = 0; k < 128; k++) acc += g_z2[b * 128 + k] * W[k * 2 + o];
        out[i] = acc;
    }
}

extern "C" void kernel_launch(void* const* d_in, const int* in_sizes, int n_in,
                              void* d_out, int out_size) {
    const float* x     = (const float*)d_in[0];
    const int*   ei    = (const int*)d_in[1];
    const float* ew    = (const float*)d_in[2];
    const int*   batch = (const int*)d_in[3];
    const float* W1  = (const float*)d_in[4];
    const float* b1  = (const float*)d_in[5];
    const float* g1  = (const float*)d_in[6];
    const float* be1 = (const float*)d_in[7];
    const float* rm1 = (const float*)d_in[8];
    const float* rv1 = (const float*)d_in[9];
    const float* W2  = (const float*)d_in[10];
    const float* b2  = (const float*)d_in[11];
    const float* g2  = (const float*)d_in[12];
    const float* be2 = (const float*)d_in[13];
    const float* rm2 = (const float*)d_in[14];
    const float* rv2 = (const float*)d_in[15];
    const float* cW1  = (const float*)d_in[16];
    const float* cb1  = (const float*)d_in[17];
    const float* cg1  = (const float*)d_in[18];
    const float* cbe1 = (const float*)d_in[19];
    const float* crm1 = (const float*)d_in[20];
    const float* crv1 = (const float*)d_in[21];
    const float* cW2  = (const float*)d_in[22];
    const float* cb2  = (const float*)d_in[23];
    const float* cg2  = (const float*)d_in[24];
    const float* cbe2 = (const float*)d_in[25];
    const float* crm2 = (const float*)d_in[26];
    const float* crv2 = (const float*)d_in[27];
    const float* cW3  = (const float*)d_in[28];
    const float* cb3  = (const float*)d_in[29];

    int DIN = in_sizes[4] / H;          // 128
    int N   = in_sizes[0] / DIN;        // 100000
    int E   = in_sizes[2];              // 1600000
    int B   = (out_size % (2 + H) == 0) ? out_size / (2 + H) : BCAP;  // 256

    const int* src = ei;
    const int* dst = ei + E;

    __half *bufH, *bufCh, *xh, *w1h, *w2h;
    float *bufC, *emb, *z1, *z2, *dinv;
    cudaGetSymbolAddress((void**)&bufH,  g_bufH);
    cudaGetSymbolAddress((void**)&bufCh, g_bufCh);
    cudaGetSymbolAddress((void**)&xh,    g_xh);
    cudaGetSymbolAddress((void**)&w1h,   g_w1h);
    cudaGetSymbolAddress((void**)&w2h,   g_w2h);
    cudaGetSymbolAddress((void**)&bufC,  g_bufC);
    cudaGetSymbolAddress((void**)&emb,   g_emb);
    cudaGetSymbolAddress((void**)&z1,    g_z1);
    cudaGetSymbolAddress((void**)&z2,    g_z2);
    cudaGetSymbolAddress((void**)&dinv,  g_dinv);

    float* out = (float*)d_out;

    // prep: conversions, histogram, dinv, BN fold, CSR build
    int zt = 2 * N + B + B * H;
    k_zero<<<(zt + 255) / 256, 256>>>(N, B);
    k_cvt<<<2048, 256>>>(x, W1, W2, N * DIN, DIN * H, H * H);
    k_hist<<<2048, 256>>>(dst, ew, E);
    k_prep<<<512, 256>>>(batch, N);
    k_bnprep<<<1, H>>>(b1, g1, be1, rm1, rv1, b2, g2, be2, rm2, rv2);
    k_scan<<<1, 1024>>>(N);
    k_build<<<2048, 256>>>(src, dst, ew, E);

    // layer 1
    dim3 gg((H + 127) / 128, (N + 127) / 128);
    k_gemm_f16<<<gg, 256>>>(xh, w1h, bufH, dinv, N, DIN, H);
    k_gather1<<<(N + 7) / 8, 256>>>(bufH, bufC, bufCh, N);

    // layer 2
    k_gemm_f16<<<gg, 256>>>(bufCh, w2h, bufH, dinv, N, H, H);
    k_gather2<<<(N + 7) / 8, 256>>>(bufH, bufC, batch, N);

    // pooling + classifier
    k_emb<<<(B * H + 255) / 256, 256>>>(out, out_size, B);
    k_mlp<<<B, 256, H * sizeof(float)>>>(emb, cW1, cb1, cg1, cbe1, crm1, crv1, z1, H, 256);
    k_mlp<<<B, 256, 256 * sizeof(float)>>>(z1, cW2, cb2, cg2, cbe2, crm2, crv2, z2, 256, 128);
    k_logits<<<(B * 2 + 255) / 256, 256>>>(cW3, cb3, out, B);
}

// round 13
// speedup vs baseline: 1.8222x; 1.0451x over previous
#include <cuda_runtime.h>
#include <cuda_fp16.h>
#include <mma.h>
#include <cstddef>

using namespace nvcuda;

#define H 256
#define NCAP 100000
#define NPAD 100096      // NCAP rounded up to 128 (full-tile GEMM stores)
#define ECAP 1600000
#define BCAP 256
#define BN_EPS 1e-5f

// ---------------- scratch (static __device__, allocation-free) ----------------
__device__ __half g_bufH[(size_t)NPAD * H];   // GEMM output h' = h*dinv (fp16)
__device__ __half g_bufCh[(size_t)NPAD * H];  // h1 in fp16 (GEMM2 A input)
__device__ __half g_xh[(size_t)NPAD * 128];   // x in fp16
__device__ __half g_w1h[128 * H];
__device__ __half g_w2h[H * H];
__device__ float  g_bufC[(size_t)NCAP * H];   // h1 fp32 (residual)
__device__ float  g_wdeg[NCAP];
__device__ int    g_count[NCAP];
__device__ int    g_rowptr[NCAP + 1];
__device__ int    g_fill[NCAP];
__device__ int    g_csrc[ECAP];
__device__ float  g_cw[ECAP];
__device__ float  g_dinv[NCAP];
__device__ float  g_cnt[BCAP];
__device__ float  g_pool[BCAP * H];
__device__ float  g_emb[BCAP * H];
__device__ float  g_z1[BCAP * 256];
__device__ float  g_z2[BCAP * 128];
__device__ float  g_bnA1[H], g_bnB1[H], g_bnA2[H], g_bnB2[H];

__device__ __forceinline__ void red_add_v4(float* addr, float x, float y, float z, float w) {
    asm volatile("red.global.add.v4.f32 [%0], {%1, %2, %3, %4};"
                 :: "l"(addr), "f"(x), "f"(y), "f"(z), "f"(w) : "memory");
}

__device__ __forceinline__ void h8_to_f8(uint4 u, float* f) {
    const __half2* h = (const __half2*)&u;
    float2 a = __half22float2(h[0]);
    float2 b = __half22float2(h[1]);
    float2 c = __half22float2(h[2]);
    float2 d = __half22float2(h[3]);
    f[0] = a.x; f[1] = a.y; f[2] = b.x; f[3] = b.y;
    f[4] = c.x; f[5] = c.y; f[6] = d.x; f[7] = d.y;
}

// ---------------- fused init: zero accumulators + fp16 conversions + BN fold ----------------
__global__ void k_init(const float* __restrict__ x, const float* __restrict__ W1,
                       const float* __restrict__ W2,
                       const float* b1, const float* g1, const float* be1,
                       const float* rm1, const float* rv1,
                       const float* b2, const float* g2, const float* be2,
                       const float* rm2, const float* rv2,
                       int n_nodes, int nb, int nx, int nw1, int nw2) {
    int gid = blockIdx.x * blockDim.x + threadIdx.x;
    int gs = gridDim.x * blockDim.x;
    // zero region
    int zt = 2 * n_nodes + nb + nb * H;
    for (int i = gid; i < zt; i += gs) {
        if (i < n_nodes) { g_wdeg[i] = 0.f; }
        else if (i < 2 * n_nodes) { g_count[i - n_nodes] = 0; }
        else if (i < 2 * n_nodes + nb) { g_cnt[i - 2 * n_nodes] = 0.f; }
        else { g_pool[i - 2 * n_nodes - nb] = 0.f; }
    }
    // fp16 conversions
    int ct = nx + nw1 + nw2;
    for (int i = gid; i < ct; i += gs) {
        if (i < nx) g_xh[i] = __float2half_rn(x[i]);
        else if (i < nx + nw1) g_w1h[i - nx] = __float2half_rn(W1[i - nx]);
        else g_w2h[i - nx - nw1] = __float2half_rn(W2[i - nx - nw1]);
    }
    // BN fold (one block)
    if (blockIdx.x == 0 && threadIdx.x < H) {
        int c = threadIdx.x;
        float A = g1[c] * rsqrtf(rv1[c] + BN_EPS);
        g_bnA1[c] = A;
        g_bnB1[c] = be1[c] + (b1[c] - rm1[c]) * A;
        float A2 = g2[c] * rsqrtf(rv2[c] + BN_EPS);
        g_bnA2[c] = A2;
        g_bnB2[c] = be2[c] + (b2[c] - rm2[c]) * A2;
    }
}

// ---------------- histogram: count + weighted degree per dst ----------------
__global__ void k_hist(const int* __restrict__ dst, const float* __restrict__ ew, int E) {
    for (int e = blockIdx.x * blockDim.x + threadIdx.x; e < E;
         e += gridDim.x * blockDim.x) {
        int d = dst[e];
        atomicAdd(&g_count[d], 1);
        atomicAdd(&g_wdeg[d], ew[e]);
    }
}

// ---------------- dinv + per-graph node counts (smem histogram) ----------------
__global__ void k_prep(const int* __restrict__ batch, int n_nodes) {
    __shared__ float hcnt[BCAP];
    int t = threadIdx.x;
    for (int i = t; i < BCAP; i += blockDim.x) hcnt[i] = 0.f;
    __syncthreads();
    for (int i = blockIdx.x * blockDim.x + t; i < n_nodes;
         i += gridDim.x * blockDim.x) {
        g_dinv[i] = rsqrtf(g_wdeg[i] + 1.0f);
        atomicAdd(&hcnt[batch[i]], 1.0f);
    }
    __syncthreads();
    for (int i = t; i < BCAP; i += blockDim.x)
        if (hcnt[i] != 0.f) atomicAdd(&g_cnt[i], hcnt[i]);
}

// ---------------- single-block exclusive scan of g_count ----------------
__global__ void k_scan(int N) {
    __shared__ int warp_sums[32];
    __shared__ int s_carry;
    int t = threadIdx.x, lane = t & 31, w = t >> 5;
    if (t == 0) s_carry = 0;
    __syncthreads();
    for (int base = 0; base < N; base += 4096) {
        int i0 = base + t * 4;
        int v[4];
        #pragma unroll
        for (int j = 0; j < 4; j++) v[j] = (i0 + j < N) ? g_count[i0 + j] : 0;
        int s = v[0] + v[1] + v[2] + v[3];
        int x = s;
        #pragma unroll
        for (int o = 1; o < 32; o <<= 1) {
            int y = __shfl_up_sync(0xffffffffu, x, o);
            if (lane >= o) x += y;
        }
        if (lane == 31) warp_sums[w] = x;
        __syncthreads();
        if (w == 0) {
            int ws = warp_sums[lane];
            #pragma unroll
            for (int o = 1; o < 32; o <<= 1) {
                int y = __shfl_up_sync(0xffffffffu, ws, o);
                if (lane >= o) ws += y;
            }
            warp_sums[lane] = ws;
        }
        __syncthreads();
        int excl = x - s + (w > 0 ? warp_sums[w - 1] : 0) + s_carry;
        #pragma unroll
        for (int j = 0; j < 4; j++) {
            if (i0 + j < N) { g_rowptr[i0 + j] = excl; g_fill[i0 + j] = excl; }
            excl += v[j];
        }
        __syncthreads();
        if (t == 1023) s_carry = excl;
        __syncthreads();
    }
    if (t == 0) g_rowptr[N] = s_carry;
}

// ---------------- scatter edges into CSR slots ----------------
__global__ void k_build(const int* __restrict__ src, const int* __restrict__ dst,
                        const float* __restrict__ ew, int E) {
    for (int e = blockIdx.x * blockDim.x + threadIdx.x; e < E;
         e += gridDim.x * blockDim.x) {
        int d = dst[e];
        int p = atomicAdd(&g_fill[d], 1);
        g_csrc[p] = src[e];
        g_cw[p] = ew[e];
    }
}

// ---------------- fp16 tensor GEMM: Ch = fp16( (diag(scale)*A) @ W ) ----------------
// CTA 128x128, BK=32, 8 warps, warp tile 64x32 (4x2 wmma m16n16k16), fp32 accum.
__global__ __launch_bounds__(256, 2)
void k_gemm_f16(const __half* __restrict__ A, const __half* __restrict__ W,
                __half* __restrict__ Ch, const float* __restrict__ scale,
                int M, int K, int Nc) {
    __shared__ __half As[128][48];   // [m][k], pad 32->48
    __shared__ __half Bs[32][136];   // [k][n], pad 128->136
    __shared__ float  St[8][16][20]; // per-warp 16x16 fp32 staging

    int t = threadIdx.x;
    int warp = t >> 5;
    int lane = t & 31;
    int wm = warp & 1;
    int wn = warp >> 1;
    int row0 = blockIdx.y * 128;
    int col0 = blockIdx.x * 128;

    wmma::fragment<wmma::accumulator, 16, 16, 16, float> acc[4][2];
    #pragma unroll
    for (int i = 0; i < 4; i++)
        #pragma unroll
        for (int j = 0; j < 2; j++)
            wmma::fill_fragment(acc[i][j], 0.f);

    for (int k0 = 0; k0 < K; k0 += 32) {
        #pragma unroll
        for (int l = 0; l < 2; l++) {
            int idx = t + l * 256;
            int r = idx >> 2, c = (idx & 3) * 8;
            int gr = row0 + r;
            uint4 u = make_uint4(0, 0, 0, 0);
            float s = 0.f;
            if (gr < M) {
                u = *(const uint4*)(A + (size_t)gr * K + k0 + c);
                s = scale[gr];
            }
            __half2 hs = __float2half2_rn(s);
            __half2* h = (__half2*)&u;
            h[0] = __hmul2(h[0], hs);
            h[1] = __hmul2(h[1], hs);
            h[2] = __hmul2(h[2], hs);
            h[3] = __hmul2(h[3], hs);
            *(uint4*)&As[r][c] = u;
        }
        #pragma unroll
        for (int l = 0; l < 2; l++) {
            int idx = t + l * 256;
            int r = idx >> 4, c = (idx & 15) * 8;
            *(uint4*)&Bs[r][c] = *(const uint4*)(W + (size_t)(k0 + r) * Nc + col0 + c);
        }
        __syncthreads();

        #pragma unroll
        for (int kk = 0; kk < 32; kk += 16) {
            wmma::fragment<wmma::matrix_a, 16, 16, 16, __half, wmma::row_major> af[4];
            #pragma unroll
            for (int i = 0; i < 4; i++)
                wmma::load_matrix_sync(af[i], &As[wm * 64 + i * 16][kk], 48);
            #pragma unroll
            for (int j = 0; j < 2; j++) {
                wmma::fragment<wmma::matrix_b, 16, 16, 16, __half, wmma::row_major> bf;
                wmma::load_matrix_sync(bf, &Bs[kk][wn * 32 + j * 16], 136);
                #pragma unroll
                for (int i = 0; i < 4; i++)
                    wmma::mma_sync(acc[i][j], af[i], bf, acc[i][j]);
            }
        }
        __syncthreads();
    }

    int sr = lane >> 1, sc = (lane & 1) * 8;
    #pragma unroll
    for (int i = 0; i < 4; i++) {
        int gr = row0 + wm * 64 + i * 16;
        #pragma unroll
        for (int j = 0; j < 2; j++) {
            int gc = col0 + wn * 32 + j * 16;
            wmma::store_matrix_sync(&St[warp][0][0], acc[i][j], 20, wmma::mem_row_major);
            __syncwarp();
            const float* p = &St[warp][sr][sc];
            __half2 h[4];
            h[0] = __floats2half2_rn(p[0], p[1]);
            h[1] = __floats2half2_rn(p[2], p[3]);
            h[2] = __floats2half2_rn(p[4], p[5]);
            h[3] = __floats2half2_rn(p[6], p[7]);
            *(uint4*)(Ch + (size_t)(gr + sr) * Nc + gc + sc) = *(uint4*)h;
            __syncwarp();
        }
    }
}

// ---------------- CSR gather core (warp per node, 8 ch/lane, fp16 h', unroll 4) ----------------
__device__ __forceinline__ void gather_acc_h(const __half* __restrict__ hp, int d, int c,
                                             float* acc) {
    int beg = __ldg(&g_rowptr[d]), end = __ldg(&g_rowptr[d + 1]);
    h8_to_f8(*(const uint4*)(hp + (size_t)d * H + c), acc);  // self-loop term
    int e = beg;
    int e4 = beg + ((end - beg) & ~3);
    for (; e < e4; e += 4) {
        int s0 = __ldg(&g_csrc[e + 0]), s1 = __ldg(&g_csrc[e + 1]);
        int s2 = __ldg(&g_csrc[e + 2]), s3 = __ldg(&g_csrc[e + 3]);
        float w0 = __ldg(&g_cw[e + 0]), w1 = __ldg(&g_cw[e + 1]);
        float w2 = __ldg(&g_cw[e + 2]), w3 = __ldg(&g_cw[e + 3]);
        uint4 u0 = *(const uint4*)(hp + (size_t)s0 * H + c);
        uint4 u1 = *(const uint4*)(hp + (size_t)s1 * H + c);
        uint4 u2 = *(const uint4*)(hp + (size_t)s2 * H + c);
        uint4 u3 = *(const uint4*)(hp + (size_t)s3 * H + c);
        float f0[8], f1[8], f2[8], f3[8];
        h8_to_f8(u0, f0);
        h8_to_f8(u1, f1);
        h8_to_f8(u2, f2);
        h8_to_f8(u3, f3);
        #pragma unroll
        for (int q = 0; q < 8; q++)
            acc[q] += w0 * f0[q] + w1 * f1[q] + w2 * f2[q] + w3 * f3[q];
    }
    for (; e < end; e++) {
        int s = __ldg(&g_csrc[e]);
        float w = __ldg(&g_cw[e]);
        uint4 u = *(const uint4*)(hp + (size_t)s * H + c);
        float f[8];
        h8_to_f8(u, f);
        #pragma unroll
        for (int q = 0; q < 8; q++) acc[q] += w * f[q];
    }
}

// ---------------- gather layer 1: fp32 residual out + fp16 GEMM2 input ----------------
__global__ void k_gather1(const __half* __restrict__ hp, float* __restrict__ out,
                          __half* __restrict__ outh, int N) {
    int lane = threadIdx.x & 31;
    int d = blockIdx.x * 8 + (threadIdx.x >> 5);
    if (d >= N) return;
    int c = lane * 8;
    float acc[8];
    gather_acc_h(hp, d, c, acc);
    float di = g_dinv[d];
    float4 A0 = *(const float4*)&g_bnA1[c], A1 = *(const float4*)&g_bnA1[c + 4];
    float4 B0 = *(const float4*)&g_bnB1[c], B1 = *(const float4*)&g_bnB1[c + 4];
    float o[8];
    o[0] = fmaxf(A0.x * (di * acc[0]) + B0.x, 0.f);
    o[1] = fmaxf(A0.y * (di * acc[1]) + B0.y, 0.f);
    o[2] = fmaxf(A0.z * (di * acc[2]) + B0.z, 0.f);
    o[3] = fmaxf(A0.w * (di * acc[3]) + B0.w, 0.f);
    o[4] = fmaxf(A1.x * (di * acc[4]) + B1.x, 0.f);
    o[5] = fmaxf(A1.y * (di * acc[5]) + B1.y, 0.f);
    o[6] = fmaxf(A1.z * (di * acc[6]) + B1.z, 0.f);
    o[7] = fmaxf(A1.w * (di * acc[7]) + B1.w, 0.f);
    *(float4*)(out + (size_t)d * H + c) = make_float4(o[0], o[1], o[2], o[3]);
    *(float4*)(out + (size_t)d * H + c + 4) = make_float4(o[4], o[5], o[6], o[7]);
    __half2 h[4];
    h[0] = __floats2half2_rn(o[0], o[1]);
    h[1] = __floats2half2_rn(o[2], o[3]);
    h[2] = __floats2half2_rn(o[4], o[5]);
    h[3] = __floats2half2_rn(o[6], o[7]);
    *(uint4*)(outh + (size_t)d * H + c) = *(uint4*)h;
}

// ---------------- gather layer 2 + residual + pool accumulate ----------------
__global__ void k_gather2(const __half* __restrict__ hp, const float* __restrict__ res,
                          const int* __restrict__ batch, int N) {
    int lane = threadIdx.x & 31;
    int d = blockIdx.x * 8 + (threadIdx.x >> 5);
    if (d >= N) return;
    int c = lane * 8;
    float acc[8];
    gather_acc_h(hp, d, c, acc);
    float di = g_dinv[d];
    float4 A0 = *(const float4*)&g_bnA2[c], A1 = *(const float4*)&g_bnA2[c + 4];
    float4 B0 = *(const float4*)&g_bnB2[c], B1 = *(const float4*)&g_bnB2[c + 4];
    float4 r0 = *(const float4*)(res + (size_t)d * H + c);
    float4 r1 = *(const float4*)(res + (size_t)d * H + c + 4);
    float v0 = fmaxf(A0.x * (di * acc[0]) + B0.x, 0.f) + r0.x;
    float v1 = fmaxf(A0.y * (di * acc[1]) + B0.y, 0.f) + r0.y;
    float v2 = fmaxf(A0.z * (di * acc[2]) + B0.z, 0.f) + r0.z;
    float v3 = fmaxf(A0.w * (di * acc[3]) + B0.w, 0.f) + r0.w;
    float v4 = fmaxf(A1.x * (di * acc[4]) + B1.x, 0.f) + r1.x;
    float v5 = fmaxf(A1.y * (di * acc[5]) + B1.y, 0.f) + r1.y;
    float v6 = fmaxf(A1.z * (di * acc[6]) + B1.z, 0.f) + r1.z;
    float v7 = fmaxf(A1.w * (di * acc[7]) + B1.w, 0.f) + r1.w;
    int b = __ldg(&batch[d]);
    red_add_v4(&g_pool[(size_t)b * H + c], v0, v1, v2, v3);
    red_add_v4(&g_pool[(size_t)b * H + c + 4], v4, v5, v6, v7);
}

// ---------------- per-graph mean + write emb output ----------------
__global__ void k_emb(float* __restrict__ out, int out_size, int nb) {
    int i = blockIdx.x * blockDim.x + threadIdx.x;
    if (i < nb * H) {
        int b = i >> 8;
        float e = g_pool[i] / fmaxf(g_cnt[b], 1.0f);
        g_emb[i] = e;
        if (out_size >= nb * 2 + nb * H)
            out[nb * 2 + i] = e;
    }
}

// ---------------- classifier MLP layer ----------------
__global__ void k_mlp(const float* __restrict__ in, const float* __restrict__ W,
                      const float* __restrict__ bb, const float* __restrict__ gg,
                      const float* __restrict__ be, const float* __restrict__ rm,
                      const float* __restrict__ rv, float* __restrict__ out,
                      int Kin, int Nout) {
    extern __shared__ float sh[];
    int b = blockIdx.x, t = threadIdx.x;
    for (int k = t; k < Kin; k += blockDim.x) sh[k] = in[(size_t)b * Kin + k];
    __syncthreads();
    if (t < Nout) {
        float acc = 0.f;
        for (int k = 0; k < Kin; k++) acc += sh[k] * W[(size_t)k * Nout + t];
        acc += bb[t];
        acc = (acc - rm[t]) * rsqrtf(rv[t] + BN_EPS) * gg[t] + be[t];
        out[(size_t)b * Nout + t] = fmaxf(acc, 0.f);
    }
}

// ---------------- final logits ----------------
__global__ void k_logits(const float* __restrict__ W, const float* __restrict__ bb,
                         float* __restrict__ out, int nb) {
    int i = blockIdx.x * blockDim.x + threadIdx.x;
    if (i < nb * 2) {
        int b = i >> 1, o = i & 1;
        float acc = bb[o];
        for (int k = 0; k < 128; k++) acc += g_z2[b * 128 + k] * W[k * 2 + o];
        out[i] = acc;
    }
}

extern "C" void kernel_launch(void* const* d_in, const int* in_sizes, int n_in,
                              void* d_out, int out_size) {
    const float* x     = (const float*)d_in[0];
    const int*   ei    = (const int*)d_in[1];
    const float* ew    = (const float*)d_in[2];
    const int*   batch = (const int*)d_in[3];
    const float* W1  = (const float*)d_in[4];
    const float* b1  = (const float*)d_in[5];
    const float* g1  = (const float*)d_in[6];
    const float* be1 = (const float*)d_in[7];
    const float* rm1 = (const float*)d_in[8];
    const float* rv1 = (const float*)d_in[9];
    const float* W2  = (const float*)d_in[10];
    const float* b2  = (const float*)d_in[11];
    const float* g2  = (const float*)d_in[12];
    const float* be2 = (const float*)d_in[13];
    const float* rm2 = (const float*)d_in[14];
    const float* rv2 = (const float*)d_in[15];
    const float* cW1  = (const float*)d_in[16];
    const float* cb1  = (const float*)d_in[17];
    const float* cg1  = (const float*)d_in[18];
    const float* cbe1 = (const float*)d_in[19];
    const float* crm1 = (const float*)d_in[20];
    const float* crv1 = (const float*)d_in[21];
    const float* cW2  = (const float*)d_in[22];
    const float* cb2  = (const float*)d_in[23];
    const float* cg2  = (const float*)d_in[24];
    const float* cbe2 = (const float*)d_in[25];
    const float* crm2 = (const float*)d_in[26];
    const float* crv2 = (const float*)d_in[27];
    const float* cW3  = (const float*)d_in[28];
    const float* cb3  = (const float*)d_in[29];

    int DIN = in_sizes[4] / H;          // 128
    int N   = in_sizes[0] / DIN;        // 100000
    int E   = in_sizes[2];              // 1600000
    int B   = (out_size % (2 + H) == 0) ? out_size / (2 + H) : BCAP;  // 256

    const int* src = ei;
    const int* dst = ei + E;

    __half *bufH, *bufCh, *xh, *w1h, *w2h;
    float *bufC, *emb, *z1, *z2, *dinv;
    cudaGetSymbolAddress((void**)&bufH,  g_bufH);
    cudaGetSymbolAddress((void**)&bufCh, g_bufCh);
    cudaGetSymbolAddress((void**)&xh,    g_xh);
    cudaGetSymbolAddress((void**)&w1h,   g_w1h);
    cudaGetSymbolAddress((void**)&w2h,   g_w2h);
    cudaGetSymbolAddress((void**)&bufC,  g_bufC);
    cudaGetSymbolAddress((void**)&emb,   g_emb);
    cudaGetSymbolAddress((void**)&z1,    g_z1);
    cudaGetSymbolAddress((void**)&z2,    g_z2);
    cudaGetSymbolAddress((void**)&dinv,  g_dinv);

    float* out = (float*)d_out;

    // prep: fused init (zero+cvt+bnfold), histogram, dinv, scan, CSR build
    k_init<<<2048, 256>>>(x, W1, W2,
                          b1, g1, be1, rm1, rv1, b2, g2, be2, rm2, rv2,
                          N, B, N * DIN, DIN * H, H * H);
    k_hist<<<2048, 256>>>(dst, ew, E);
    k_prep<<<512, 256>>>(batch, N);
    k_scan<<<1, 1024>>>(N);
    k_build<<<2048, 256>>>(src, dst, ew, E);

    // layer 1
    dim3 gg((H + 127) / 128, (N + 127) / 128);
    k_gemm_f16<<<gg, 256>>>(xh, w1h, bufH, dinv, N, DIN, H);
    k_gather1<<<(N + 7) / 8, 256>>>(bufH, bufC, bufCh, N);

    // layer 2
    k_gemm_f16<<<gg, 256>>>(bufCh, w2h, bufH, dinv, N, H, H);
    k_gather2<<<(N + 7) / 8, 256>>>(bufH, bufC, batch, N);

    // pooling + classifier
    k_emb<<<(B * H + 255) / 256, 256>>>(out, out_size, B);
    k_mlp<<<B, 256, H * sizeof(float)>>>(emb, cW1, cb1, cg1, cbe1, crm1, crv1, z1, H, 256);
    k_mlp<<<B, 256, 256 * sizeof(float)>>>(z1, cW2, cb2, cg2, cbe2, crm2, crv2, z2, 256, 128);
    k_logits<<<(B * 2 + 255) / 256, 256>>>(cW3, cb3, out, B);
}